// round 11
// baseline (speedup 1.0000x reference)
#include <cuda_runtime.h>
#include <cuda_bf16.h>
#include <math.h>
#include <stdint.h>

// Problem constants: RetentionHead  B=4, T=4096, C=1024, H=128
#define BN 4
#define TN 4096
#define CN 1024
#define HN 128
#define LN 128
#define NCN (TN / LN)          // 32 chunks per batch
#define MN (BN * TN)           // 16384 rows
#define NPROJ 384
#define GAMMA 0.96875f
#define SCALE 0.03125f         // C^-0.5

typedef unsigned long long ull;

// ---------------- mma.sync / ldmatrix / cp.async helpers -------------------
__device__ __forceinline__ uint32_t smem_u32(const void* p) {
    uint32_t a;
    asm("{ .reg .u64 t; cvta.to.shared.u64 t, %1; cvt.u32.u64 %0, t; }" : "=r"(a) : "l"(p));
    return a;
}
__device__ __forceinline__ void cp16(uint32_t s, const void* g) {
    asm volatile("cp.async.cg.shared.global [%0], [%1], 16;" :: "r"(s), "l"(g));
}
__device__ __forceinline__ void cp_commit() {
    asm volatile("cp.async.commit_group;" ::: "memory");
}
__device__ __forceinline__ void ldm_x4(uint32_t* r, uint32_t addr) {
    asm volatile("ldmatrix.sync.aligned.m8n8.x4.shared.b16 {%0,%1,%2,%3}, [%4];"
                 : "=r"(r[0]), "=r"(r[1]), "=r"(r[2]), "=r"(r[3]) : "r"(addr));
}
__device__ __forceinline__ void ldm_x4_t(uint32_t* r, uint32_t addr) {
    asm volatile("ldmatrix.sync.aligned.m8n8.x4.trans.shared.b16 {%0,%1,%2,%3}, [%4];"
                 : "=r"(r[0]), "=r"(r[1]), "=r"(r[2]), "=r"(r[3]) : "r"(addr));
}
__device__ __forceinline__ void mma_bf16(float* d, const uint32_t* a,
                                         uint32_t b0, uint32_t b1) {
    asm volatile(
        "mma.sync.aligned.m16n8k16.row.col.f32.bf16.bf16.f32 "
        "{%0,%1,%2,%3}, {%4,%5,%6,%7}, {%8,%9}, {%0,%1,%2,%3};"
        : "+f"(d[0]), "+f"(d[1]), "+f"(d[2]), "+f"(d[3])
        : "r"(a[0]), "r"(a[1]), "r"(a[2]), "r"(a[3]), "r"(b0), "r"(b1));
}
// 3-product split-2 mma: hi*hi + lo*hi + hi*lo
__device__ __forceinline__ void mma3(float* d, const uint32_t* ah, const uint32_t* al,
                                     uint32_t bh0, uint32_t bh1,
                                     uint32_t bl0, uint32_t bl1) {
    mma_bf16(d, ah, bh0, bh1);
    mma_bf16(d, al, bh0, bh1);
    mma_bf16(d, ah, bl0, bl1);
}
__device__ __forceinline__ uint32_t pack_bf2(float a, float b) {
    __nv_bfloat162 t = __floats2bfloat162_rn(a, b);
    return *reinterpret_cast<uint32_t*>(&t);
}
__device__ __forceinline__ void split_pair(float a, float b, uint32_t& hi, uint32_t& lo) {
    __nv_bfloat16 ah = __float2bfloat16_rn(a);
    __nv_bfloat16 bh = __float2bfloat16_rn(b);
    __nv_bfloat162 hh; hh.x = ah; hh.y = bh;
    hi = *reinterpret_cast<uint32_t*>(&hh);
    lo = pack_bf2(a - __bfloat162float(ah), b - __bfloat162float(bh));
}
__device__ __forceinline__ float bf2sum(uint32_t hw, uint32_t lw, int half) {
    __nv_bfloat162 h = *reinterpret_cast<__nv_bfloat162*>(&hw);
    __nv_bfloat162 l = *reinterpret_cast<__nv_bfloat162*>(&lw);
    return half ? (__bfloat162float(h.y) + __bfloat162float(l.y))
                : (__bfloat162float(h.x) + __bfloat162float(l.x));
}

// ---------------- scratch (device globals) ---------------------------------
__device__ float g_A[BN * NCN * HN * HN];
__device__ __nv_bfloat16 g_qh[MN * HN], g_ql[MN * HN];
__device__ __nv_bfloat16 g_kh[MN * HN], g_kl[MN * HN];
__device__ __nv_bfloat16 g_vh[MN * HN], g_vl[MN * HN];
__device__ __nv_bfloat16 g_Sh[BN * NCN * HN * HN], g_Sl[BN * NCN * HN * HN];
__device__ __nv_bfloat16 g_wt_hi[NPROJ * CN];
__device__ __nv_bfloat16 g_wt_lo[NPROJ * CN];

// ===========================================================================
// Kernel 0: W prep — transpose + split fp32 W[k][n] -> bf16 hi/lo [mat*128+n][k]
// ===========================================================================
__global__ void wprep_kernel(const float* __restrict__ Wq,
                             const float* __restrict__ Wk,
                             const float* __restrict__ Wv)
{
    int k = blockIdx.x;
    int mat = blockIdx.y;
    int n = threadIdx.x;
    const float* W = (mat == 0) ? Wq : (mat == 1) ? Wk : Wv;
    float w = W[(size_t)k * HN + n];
    __nv_bfloat16 hi = __float2bfloat16_rn(w);
    size_t off = ((size_t)mat * HN + n) * CN + k;
    g_wt_hi[off] = hi;
    g_wt_lo[off] = __float2bfloat16_rn(w - __bfloat162float(hi));
}

// ===========================================================================
// Kernel 1: projection GEMM, 512 threads, warp grid 4x4 (32x32 warp tile).
// ===========================================================================
#define OFF_A_HI 0
#define OFF_A_LO 8192
#define OFF_B_HI 16384
#define OFF_B_LO 24576
#define BUF_SZ 32768
#define NKSTEP (CN / 32)

__global__ __launch_bounds__(512) void proj_mma_kernel(const float* __restrict__ x)
{
    extern __shared__ char sm[];
    const uint32_t sbase = smem_u32(sm);
    const int tid  = threadIdx.x;
    const int wid  = tid >> 5;
    const int lane = tid & 31;
    const int wm   = wid & 3;        // 4 warp-rows (32 M each)
    const int wn   = wid >> 2;       // 4 warp-cols (32 N each)
    const int mat  = blockIdx.x;
    const int m0   = blockIdx.y * 128;
    const int n0   = mat * 128;

    // per-thread load coords: 128 rows x 4 chunks-of-8 = 512 units, 1/thread
    const int arow0 = tid >> 2;
    const int ach0  = tid & 3;

    float acc[2][4][4];
#pragma unroll
    for (int a = 0; a < 2; ++a)
#pragma unroll
        for (int b = 0; b < 4; ++b)
#pragma unroll
            for (int c = 0; c < 4; ++c) acc[a][b][c] = 0.0f;

    // prologue
    float4 apre0, apre1;
    {
        const float* src = &x[(size_t)(m0 + arow0) * CN + ach0 * 8];
        apre0 = *reinterpret_cast<const float4*>(src);
        apre1 = *reinterpret_cast<const float4*>(src + 4);
        uint32_t so = (uint32_t)(arow0 * 64 + ((ach0 ^ ((arow0 >> 1) & 3)) * 16));
        cp16(sbase + OFF_B_HI + so, &g_wt_hi[(size_t)(n0 + arow0) * CN + ach0 * 8]);
        cp16(sbase + OFF_B_LO + so, &g_wt_lo[(size_t)(n0 + arow0) * CN + ach0 * 8]);
        cp_commit();
    }

    for (int ks = 0; ks < NKSTEP; ++ks) {
        const uint32_t sbuf = sbase + (uint32_t)(ks & 1) * BUF_SZ;
        // split + store A regs into Abuf[cur]
        {
            float f[8] = {apre0.x, apre0.y, apre0.z, apre0.w,
                          apre1.x, apre1.y, apre1.z, apre1.w};
            uint4 vh, vl;
            uint32_t* ph = &vh.x;
            uint32_t* pl = &vl.x;
#pragma unroll
            for (int q = 0; q < 4; ++q) split_pair(f[2*q], f[2*q+1], ph[q], pl[q]);
            uint32_t so = (uint32_t)(arow0 * 64 + ((ach0 ^ ((arow0 >> 1) & 3)) * 16));
            *reinterpret_cast<uint4*>(sm + (ks & 1) * BUF_SZ + OFF_A_HI + so) = vh;
            *reinterpret_cast<uint4*>(sm + (ks & 1) * BUF_SZ + OFF_A_LO + so) = vl;
        }
        // prefetch next
        if (ks + 1 < NKSTEP) {
            const int k0n = (ks + 1) * 32;
            const uint32_t snext = sbase + (uint32_t)((ks + 1) & 1) * BUF_SZ;
            const float* src = &x[(size_t)(m0 + arow0) * CN + k0n + ach0 * 8];
            apre0 = *reinterpret_cast<const float4*>(src);
            apre1 = *reinterpret_cast<const float4*>(src + 4);
            uint32_t so = (uint32_t)(arow0 * 64 + ((ach0 ^ ((arow0 >> 1) & 3)) * 16));
            cp16(snext + OFF_B_HI + so, &g_wt_hi[(size_t)(n0 + arow0) * CN + k0n + ach0 * 8]);
            cp16(snext + OFF_B_LO + so, &g_wt_lo[(size_t)(n0 + arow0) * CN + k0n + ach0 * 8]);
            cp_commit();
            asm volatile("cp.async.wait_group 1;" ::: "memory");
        } else {
            asm volatile("cp.async.wait_group 0;" ::: "memory");
        }
        __syncthreads();

#pragma unroll
        for (int kk = 0; kk < 2; ++kk) {
            uint32_t ah[2][4], al[2][4];
            const int arow = lane & 15;
            const int ach  = kk * 2 + (lane >> 4);
#pragma unroll
            for (int mf = 0; mf < 2; ++mf) {
                int row = wm * 32 + mf * 16 + arow;
                uint32_t so = (uint32_t)(row * 64 + ((ach ^ ((row >> 1) & 3)) * 16));
                ldm_x4(ah[mf], sbuf + OFF_A_HI + so);
                ldm_x4(al[mf], sbuf + OFF_A_LO + so);
            }
            uint32_t bh[2][4], bl[2][4];
            const int brow = (lane & 7) + ((lane >> 4) & 1) * 8;
            const int bch  = kk * 2 + ((lane >> 3) & 1);
#pragma unroll
            for (int nf2 = 0; nf2 < 2; ++nf2) {
                int row = wn * 32 + nf2 * 16 + brow;
                uint32_t so = (uint32_t)(row * 64 + ((bch ^ ((row >> 1) & 3)) * 16));
                ldm_x4(bh[nf2], sbuf + OFF_B_HI + so);
                ldm_x4(bl[nf2], sbuf + OFF_B_LO + so);
            }
#pragma unroll
            for (int mf = 0; mf < 2; ++mf)
#pragma unroll
                for (int nf = 0; nf < 4; ++nf)
                    mma3(acc[mf][nf], ah[mf], al[mf],
                         bh[nf >> 1][(nf & 1) * 2], bh[nf >> 1][(nf & 1) * 2 + 1],
                         bl[nf >> 1][(nf & 1) * 2], bl[nf >> 1][(nf & 1) * 2 + 1]);
        }
        __syncthreads();
    }

    const float sc = (mat == 0) ? SCALE : 1.0f;
    __nv_bfloat16* dsth = (mat == 0) ? g_qh : (mat == 1) ? g_kh : g_vh;
    __nv_bfloat16* dstl = (mat == 0) ? g_ql : (mat == 1) ? g_kl : g_vl;
    const int r0 = lane >> 2;
    const int c0 = (lane & 3) * 2;
#pragma unroll
    for (int mf = 0; mf < 2; ++mf) {
#pragma unroll
        for (int nf = 0; nf < 4; ++nf) {
            int row = m0 + wm * 32 + mf * 16 + r0;
            int col = wn * 32 + nf * 8 + c0;
            float d0 = acc[mf][nf][0] * sc, d1 = acc[mf][nf][1] * sc;
            float d2 = acc[mf][nf][2] * sc, d3 = acc[mf][nf][3] * sc;
            uint32_t h0, l0, h1, l1;
            split_pair(d0, d1, h0, l0);
            split_pair(d2, d3, h1, l1);
            *reinterpret_cast<uint32_t*>(&dsth[(size_t)row * HN + col])       = h0;
            *reinterpret_cast<uint32_t*>(&dstl[(size_t)row * HN + col])       = l0;
            *reinterpret_cast<uint32_t*>(&dsth[(size_t)(row + 8) * HN + col]) = h1;
            *reinterpret_cast<uint32_t*>(&dstl[(size_t)(row + 8) * HN + col]) = l1;
        }
    }
}

// ===========================================================================
// Kernel 2: chunkkv via mma, 512 threads, warp grid 4x4.
// ===========================================================================
__global__ __launch_bounds__(512) void chunkkv_mma()
{
    __shared__ __align__(16) char KHI[8192], KLO[8192], VHI[8192], VLO[8192];
    __shared__ float gp[132];

    const int c = blockIdx.x;
    const int b = blockIdx.y;
    const size_t rowbase = (size_t)(b * TN + c * LN);
    const __nv_bfloat16* __restrict__ khp = g_kh + rowbase * HN;
    const __nv_bfloat16* __restrict__ klp = g_kl + rowbase * HN;
    const __nv_bfloat16* __restrict__ vhp = g_vh + rowbase * HN;
    const __nv_bfloat16* __restrict__ vlp = g_vl + rowbase * HN;
    float* __restrict__ ap = g_A + (size_t)(b * NCN + c) * HN * HN;

    const int tid  = threadIdx.x;
    const int wid  = tid >> 5;
    const int lane = tid & 31;
    const int wm   = wid & 3;
    const int wn   = wid >> 2;

    if (tid < 132) gp[tid] = powf(GAMMA, (float)tid);
    const uint32_t skh = smem_u32(KHI), skl = smem_u32(KLO);
    const uint32_t svh = smem_u32(VHI), svl = smem_u32(VLO);
    __syncthreads();

    float acc[2][4][4];
#pragma unroll
    for (int a = 0; a < 2; ++a)
#pragma unroll
        for (int e = 0; e < 4; ++e)
#pragma unroll
            for (int f = 0; f < 4; ++f) acc[a][e][f] = 0.0f;

    for (int jt = 0; jt < 4; ++jt) {
        __syncthreads();
        // decayed k split stripe [32 j][128 hk]: 32x16 chunks = 512, 1/thread
        {
            int row = tid >> 4;
            int ch  = tid & 15;
            int j   = jt * 32 + row;
            float w = gp[LN - j];
            uint4 dh = *reinterpret_cast<const uint4*>(&khp[(size_t)j * HN + ch * 8]);
            uint4 dl = *reinterpret_cast<const uint4*>(&klp[(size_t)j * HN + ch * 8]);
            const uint32_t* hw = &dh.x;
            const uint32_t* lw = &dl.x;
            uint4 vh4, vl4;
            uint32_t* ph = &vh4.x;
            uint32_t* pl = &vl4.x;
#pragma unroll
            for (int q = 0; q < 4; ++q) {
                float f0 = bf2sum(hw[q], lw[q], 0) * w;
                float f1 = bf2sum(hw[q], lw[q], 1) * w;
                split_pair(f0, f1, ph[q], pl[q]);
            }
            uint32_t dst = (uint32_t)(row * 256 + ((ch ^ (row & 7)) * 16));
            *reinterpret_cast<uint4*>(KHI + dst) = vh4;
            *reinterpret_cast<uint4*>(KLO + dst) = vl4;
            // v stripe
            uint4 evh = *reinterpret_cast<const uint4*>(&vhp[(size_t)j * HN + ch * 8]);
            uint4 evl = *reinterpret_cast<const uint4*>(&vlp[(size_t)j * HN + ch * 8]);
            *reinterpret_cast<uint4*>(VHI + dst) = evh;
            *reinterpret_cast<uint4*>(VLO + dst) = evl;
        }
        __syncthreads();

#pragma unroll
        for (int kk = 0; kk < 2; ++kk) {
            uint32_t ah[2][4], al[2][4];
            const int arow = kk * 16 + (lane & 7) + ((lane >> 4) & 1) * 8;
#pragma unroll
            for (int mf = 0; mf < 2; ++mf) {
                int ach = wm * 4 + mf * 2 + ((lane >> 3) & 1);
                uint32_t so = (uint32_t)(arow * 256 + ((ach ^ (arow & 7)) * 16));
                ldm_x4_t(ah[mf], skh + so);
                ldm_x4_t(al[mf], skl + so);
            }
            uint32_t bh[2][4], bl[2][4];
            const int brow = kk * 16 + (lane & 7) + ((lane >> 3) & 1) * 8;
#pragma unroll
            for (int nf2 = 0; nf2 < 2; ++nf2) {
                int bch = wn * 4 + nf2 * 2 + ((lane >> 4) & 1);
                uint32_t so = (uint32_t)(brow * 256 + ((bch ^ (brow & 7)) * 16));
                ldm_x4_t(bh[nf2], svh + so);
                ldm_x4_t(bl[nf2], svl + so);
            }
#pragma unroll
            for (int mf = 0; mf < 2; ++mf)
#pragma unroll
                for (int nf = 0; nf < 4; ++nf)
                    mma3(acc[mf][nf], ah[mf], al[mf],
                         bh[nf >> 1][(nf & 1) * 2], bh[nf >> 1][(nf & 1) * 2 + 1],
                         bl[nf >> 1][(nf & 1) * 2], bl[nf >> 1][(nf & 1) * 2 + 1]);
        }
    }

    const int r0 = lane >> 2;
    const int c0 = (lane & 3) * 2;
#pragma unroll
    for (int mf = 0; mf < 2; ++mf)
#pragma unroll
        for (int nf = 0; nf < 4; ++nf) {
            int row = wm * 32 + mf * 16 + r0;
            int col = wn * 32 + nf * 8 + c0;
            float2 v0 = {acc[mf][nf][0], acc[mf][nf][1]};
            float2 v1 = {acc[mf][nf][2], acc[mf][nf][3]};
            *reinterpret_cast<float2*>(&ap[(size_t)row * HN + col])       = v0;
            *reinterpret_cast<float2*>(&ap[(size_t)(row + 8) * HN + col]) = v1;
        }
}

// ===========================================================================
// Kernel 3: prefix scan with batched MLP loads (unchanged).
// ===========================================================================
__global__ void scan_kernel()
{
    int idx = blockIdx.x * blockDim.x + threadIdx.x;
    if (idx >= BN * HN * HN) return;
    int b = idx / (HN * HN);
    int e = idx % (HN * HN);
    const float gL = powf(GAMMA, (float)LN);
    const size_t base = (size_t)b * NCN * HN * HN + e;

    float a[NCN];
#pragma unroll
    for (int c = 0; c < NCN; ++c)
        a[c] = g_A[base + (size_t)c * HN * HN];

    float S = 0.0f;
#pragma unroll
    for (int c = 0; c < NCN; ++c) {
        size_t off = base + (size_t)c * HN * HN;
        __nv_bfloat16 hi = __float2bfloat16_rn(S);
        g_Sh[off] = hi;
        g_Sl[off] = __float2bfloat16_rn(S - __bfloat162float(hi));
        S = fmaf(S, gL, a[c]);
    }
}

// ===========================================================================
// Kernel 4: out via mma, 512 threads, warp grid 4x4, fused phase 1 + 2b.
// ===========================================================================
#define OP_HI 0
#define OP_LO 32768
#define OSA   65536
#define OSB   81920
#define OSC   98304
#define OUT_SMEM 114688

__global__ __launch_bounds__(512) void out_mma(float* __restrict__ out)
{
    extern __shared__ char sm[];
    __shared__ float gp[128];
    const uint32_t sb = smem_u32(sm);

    const int c = blockIdx.x;
    const int b = blockIdx.y;
    const size_t rowbase = (size_t)(b * TN + c * LN);
    const __nv_bfloat16* __restrict__ qh = g_qh + rowbase * HN;
    const __nv_bfloat16* __restrict__ ql = g_ql + rowbase * HN;
    const __nv_bfloat16* __restrict__ kh = g_kh + rowbase * HN;
    const __nv_bfloat16* __restrict__ kl = g_kl + rowbase * HN;
    const __nv_bfloat16* __restrict__ vh = g_vh + rowbase * HN;
    const __nv_bfloat16* __restrict__ vl = g_vl + rowbase * HN;
    const __nv_bfloat16* __restrict__ Sh = g_Sh + (size_t)(b * NCN + c) * HN * HN;
    const __nv_bfloat16* __restrict__ Sl = g_Sl + (size_t)(b * NCN + c) * HN * HN;

    const int tid  = threadIdx.x;
    const int wid  = tid >> 5;
    const int lane = tid & 31;
    const int wm   = wid & 3;
    const int wn   = wid >> 2;

    if (tid < 128) gp[tid] = powf(GAMMA, (float)tid);
    __syncthreads();

    // 128x32 bf16 tile: 128 rows x 4 chunks = 512 units, 1/thread
    auto copy128x32 = [&](int dstOff, const __nv_bfloat16* src, int h0) {
        int row = tid >> 2;
        int ch  = tid & 3;
        uint4 d = *reinterpret_cast<const uint4*>(&src[(size_t)row * HN + h0 + ch * 8]);
        *reinterpret_cast<uint4*>(sm + dstOff + row * 64 +
                                  ((ch ^ ((row >> 1) & 3)) * 16)) = d;
    };
    // 32x128 bf16 tile: 32 rows x 16 chunks = 512 units, 1/thread
    auto copy32x128 = [&](int dstOff, const __nv_bfloat16* src) {
        int row = tid >> 4;
        int ch  = tid & 15;
        uint4 d = *reinterpret_cast<const uint4*>(&src[(size_t)row * HN + ch * 8]);
        *reinterpret_cast<uint4*>(sm + dstOff + row * 256 +
                                  ((ch ^ (row & 7)) * 16)) = d;
    };

    // ---------------- fused phase 1 + 2b: P = Q K^T, O = Q S ---------------
    float pAcc[2][4][4], oAcc[2][4][4];
#pragma unroll
    for (int a = 0; a < 2; ++a)
#pragma unroll
        for (int e = 0; e < 4; ++e)
#pragma unroll
            for (int f = 0; f < 4; ++f) { pAcc[a][e][f] = 0.0f; oAcc[a][e][f] = 0.0f; }

    const bool p1skip = (wm < wn);   // rows [wm*32..+32) all masked vs cols [wn*32..)
    for (int ks = 0; ks < 4; ++ks) {
        __syncthreads();
        copy128x32(OSA,        qh, ks * 32);
        copy128x32(OSA + 8192, ql, ks * 32);
        copy128x32(OSB,        kh, ks * 32);
        copy128x32(OSB + 8192, kl, ks * 32);
        copy32x128(OSC,        Sh + (size_t)ks * 32 * HN);
        copy32x128(OSC + 8192, Sl + (size_t)ks * 32 * HN);
        __syncthreads();
#pragma unroll
        for (int kk = 0; kk < 2; ++kk) {
            // shared A fragments (Q)
            uint32_t ah[2][4], al[2][4];
            const int arow = lane & 15;
            const int ach  = kk * 2 + (lane >> 4);
#pragma unroll
            for (int mf = 0; mf < 2; ++mf) {
                int row = wm * 32 + mf * 16 + arow;
                uint32_t so = (uint32_t)(row * 64 + ((ach ^ ((row >> 1) & 3)) * 16));
                ldm_x4(ah[mf], sb + OSA + so);
                ldm_x4(al[mf], sb + OSA + 8192 + so);
            }
            // phase 1 B fragments (K)
            if (!p1skip) {
                uint32_t bh[2][4], bl[2][4];
                const int brow = (lane & 7) + ((lane >> 4) & 1) * 8;
                const int bch  = kk * 2 + ((lane >> 3) & 1);
#pragma unroll
                for (int nf2 = 0; nf2 < 2; ++nf2) {
                    int row = wn * 32 + nf2 * 16 + brow;
                    uint32_t so = (uint32_t)(row * 64 + ((bch ^ ((row >> 1) & 3)) * 16));
                    ldm_x4(bh[nf2], sb + OSB + so);
                    ldm_x4(bl[nf2], sb + OSB + 8192 + so);
                }
#pragma unroll
                for (int mf = 0; mf < 2; ++mf)
#pragma unroll
                    for (int nf = 0; nf < 4; ++nf)
                        mma3(pAcc[mf][nf], ah[mf], al[mf],
                             bh[nf >> 1][(nf & 1) * 2], bh[nf >> 1][(nf & 1) * 2 + 1],
                             bl[nf >> 1][(nf & 1) * 2], bl[nf >> 1][(nf & 1) * 2 + 1]);
            }
            // phase 2b B fragments (S, trans)
            {
                uint32_t bh[2][4], bl[2][4];
                const int brow = kk * 16 + (lane & 7) + ((lane >> 3) & 1) * 8;
#pragma unroll
                for (int nf2 = 0; nf2 < 2; ++nf2) {
                    int bch = wn * 4 + nf2 * 2 + ((lane >> 4) & 1);
                    uint32_t so = (uint32_t)(brow * 256 + ((bch ^ (brow & 7)) * 16));
                    ldm_x4_t(bh[nf2], sb + OSC + so);
                    ldm_x4_t(bl[nf2], sb + OSC + 8192 + so);
                }
#pragma unroll
                for (int mf = 0; mf < 2; ++mf)
#pragma unroll
                    for (int nf = 0; nf < 4; ++nf)
                        mma3(oAcc[mf][nf], ah[mf], al[mf],
                             bh[nf >> 1][(nf & 1) * 2], bh[nf >> 1][(nf & 1) * 2 + 1],
                             bl[nf >> 1][(nf & 1) * 2], bl[nf >> 1][(nf & 1) * 2 + 1]);
            }
        }
    }

    // ---------------- mask + split + store P to smem; scale O --------------
    {
        const int r0 = lane >> 2;
        const int c0 = (lane & 3) * 2;
#pragma unroll
        for (int mf = 0; mf < 2; ++mf) {
            int i0 = wm * 32 + mf * 16 + r0;
            int i1 = i0 + 8;
            float g0 = gp[i0], g1 = gp[i1];
#pragma unroll
            for (int nf = 0; nf < 4; ++nf) {
                int j0 = wn * 32 + nf * 8 + c0;
                int j1 = j0 + 1;
                float d0 = (i0 >= j0) ? pAcc[mf][nf][0] * gp[i0 - j0] : 0.0f;
                float d1 = (i0 >= j1) ? pAcc[mf][nf][1] * gp[i0 - j1] : 0.0f;
                float d2 = (i1 >= j0) ? pAcc[mf][nf][2] * gp[i1 - j0] : 0.0f;
                float d3 = (i1 >= j1) ? pAcc[mf][nf][3] * gp[i1 - j1] : 0.0f;
                uint32_t h0, l0, h1, l1;
                split_pair(d0, d1, h0, l0);
                split_pair(d2, d3, h1, l1);
                uint32_t a0 = (uint32_t)(i0 * 256 + (((j0 >> 3) ^ (i0 & 7)) * 16) + (j0 & 7) * 2);
                uint32_t a1 = (uint32_t)(i1 * 256 + (((j0 >> 3) ^ (i1 & 7)) * 16) + (j0 & 7) * 2);
                *reinterpret_cast<uint32_t*>(sm + OP_HI + a0) = h0;
                *reinterpret_cast<uint32_t*>(sm + OP_LO + a0) = l0;
                *reinterpret_cast<uint32_t*>(sm + OP_HI + a1) = h1;
                *reinterpret_cast<uint32_t*>(sm + OP_LO + a1) = l1;
                oAcc[mf][nf][0] *= g0;
                oAcc[mf][nf][1] *= g0;
                oAcc[mf][nf][2] *= g1;
                oAcc[mf][nf][3] *= g1;
            }
        }
    }

    // ---------------- phase 2a: O += P @ V ---------------------------------
    for (int jt = 0; jt < 4; ++jt) {
        __syncthreads();
        copy32x128(OSB,        vh + (size_t)jt * 32 * HN);
        copy32x128(OSB + 8192, vl + (size_t)jt * 32 * HN);
        __syncthreads();
        if (jt > wm) continue;   // rows [wm*32..+32) never see j >= (wm+1)*32
#pragma unroll
        for (int kk = 0; kk < 2; ++kk) {
            const int ks = jt * 2 + kk;
            uint32_t ah[2][4], al[2][4];
            const int arow = lane & 15;
            const int ach  = ks * 2 + (lane >> 4);
#pragma unroll
            for (int mf = 0; mf < 2; ++mf) {
                int row = wm * 32 + mf * 16 + arow;
                uint32_t so = (uint32_t)(row * 256 + ((ach ^ (row & 7)) * 16));
                ldm_x4(ah[mf], sb + OP_HI + so);
                ldm_x4(al[mf], sb + OP_LO + so);
            }
            uint32_t bh[2][4], bl[2][4];
            const int brow = kk * 16 + (lane & 7) + ((lane >> 3) & 1) * 8;
#pragma unroll
            for (int nf2 = 0; nf2 < 2; ++nf2) {
                int bch = wn * 4 + nf2 * 2 + ((lane >> 4) & 1);
                uint32_t so = (uint32_t)(brow * 256 + ((bch ^ (brow & 7)) * 16));
                ldm_x4_t(bh[nf2], sb + OSB + so);
                ldm_x4_t(bl[nf2], sb + OSB + 8192 + so);
            }
#pragma unroll
            for (int mf = 0; mf < 2; ++mf)
#pragma unroll
                for (int nf = 0; nf < 4; ++nf)
                    mma3(oAcc[mf][nf], ah[mf], al[mf],
                         bh[nf >> 1][(nf & 1) * 2], bh[nf >> 1][(nf & 1) * 2 + 1],
                         bl[nf >> 1][(nf & 1) * 2], bl[nf >> 1][(nf & 1) * 2 + 1]);
        }
    }

    // ---------------- store O ----------------------------------------------
    {
        const int r0 = lane >> 2;
        const int c0 = (lane & 3) * 2;
#pragma unroll
        for (int mf = 0; mf < 2; ++mf)
#pragma unroll
            for (int nf = 0; nf < 4; ++nf) {
                size_t row = rowbase + wm * 32 + mf * 16 + r0;
                int col = wn * 32 + nf * 8 + c0;
                float2 v0 = {oAcc[mf][nf][0], oAcc[mf][nf][1]};
                float2 v1 = {oAcc[mf][nf][2], oAcc[mf][nf][3]};
                *reinterpret_cast<float2*>(&out[row * HN + col])       = v0;
                *reinterpret_cast<float2*>(&out[(row + 8) * HN + col]) = v1;
            }
    }
}

// ===========================================================================
extern "C" void kernel_launch(void* const* d_in, const int* in_sizes, int n_in,
                              void* d_out, int out_size)
{
    const float* x  = (const float*)d_in[0];
    const float* Wq = (const float*)d_in[1];
    const float* Wk = (const float*)d_in[2];
    const float* Wv = (const float*)d_in[3];
    float* out = (float*)d_out;

    cudaFuncSetAttribute(proj_mma_kernel, cudaFuncAttributeMaxDynamicSharedMemorySize,
                         2 * BUF_SZ);
    cudaFuncSetAttribute(out_mma, cudaFuncAttributeMaxDynamicSharedMemorySize,
                         OUT_SMEM);

    wprep_kernel<<<dim3(CN, 3), HN>>>(Wq, Wk, Wv);
    proj_mma_kernel<<<dim3(3, MN / 128), 512, 2 * BUF_SZ>>>(x);
    chunkkv_mma<<<dim3(NCN, BN), 512>>>();
    scan_kernel<<<(BN * HN * HN + 255) / 256, 256>>>();
    out_mma<<<dim3(NCN, BN), 512, OUT_SMEM>>>(out);
}

// round 12
// speedup vs baseline: 1.1033x; 1.1033x over previous
#include <cuda_runtime.h>
#include <cuda_bf16.h>
#include <math.h>
#include <stdint.h>

// Problem constants: RetentionHead  B=4, T=4096, C=1024, H=128
#define BN 4
#define TN 4096
#define CN 1024
#define HN 128
#define LN 128
#define NCN (TN / LN)          // 32 chunks per batch
#define MN (BN * TN)           // 16384 rows
#define NPROJ 384
#define GAMMA 0.96875f
#define SCALE 0.03125f         // C^-0.5

typedef unsigned long long ull;

// ---------------- mma.sync / ldmatrix / cp.async helpers -------------------
__device__ __forceinline__ uint32_t smem_u32(const void* p) {
    uint32_t a;
    asm("{ .reg .u64 t; cvta.to.shared.u64 t, %1; cvt.u32.u64 %0, t; }" : "=r"(a) : "l"(p));
    return a;
}
__device__ __forceinline__ void cp16(uint32_t s, const void* g) {
    asm volatile("cp.async.cg.shared.global [%0], [%1], 16;" :: "r"(s), "l"(g));
}
__device__ __forceinline__ void cp_commit() {
    asm volatile("cp.async.commit_group;" ::: "memory");
}
__device__ __forceinline__ void ldm_x4(uint32_t* r, uint32_t addr) {
    asm volatile("ldmatrix.sync.aligned.m8n8.x4.shared.b16 {%0,%1,%2,%3}, [%4];"
                 : "=r"(r[0]), "=r"(r[1]), "=r"(r[2]), "=r"(r[3]) : "r"(addr));
}
__device__ __forceinline__ void ldm_x4_t(uint32_t* r, uint32_t addr) {
    asm volatile("ldmatrix.sync.aligned.m8n8.x4.trans.shared.b16 {%0,%1,%2,%3}, [%4];"
                 : "=r"(r[0]), "=r"(r[1]), "=r"(r[2]), "=r"(r[3]) : "r"(addr));
}
__device__ __forceinline__ void mma_bf16(float* d, const uint32_t* a,
                                         uint32_t b0, uint32_t b1) {
    asm volatile(
        "mma.sync.aligned.m16n8k16.row.col.f32.bf16.bf16.f32 "
        "{%0,%1,%2,%3}, {%4,%5,%6,%7}, {%8,%9}, {%0,%1,%2,%3};"
        : "+f"(d[0]), "+f"(d[1]), "+f"(d[2]), "+f"(d[3])
        : "r"(a[0]), "r"(a[1]), "r"(a[2]), "r"(a[3]), "r"(b0), "r"(b1));
}
// 3-product split-2 mma: hi*hi + lo*hi + hi*lo
__device__ __forceinline__ void mma3(float* d, const uint32_t* ah, const uint32_t* al,
                                     uint32_t bh0, uint32_t bh1,
                                     uint32_t bl0, uint32_t bl1) {
    mma_bf16(d, ah, bh0, bh1);
    mma_bf16(d, al, bh0, bh1);
    mma_bf16(d, ah, bl0, bl1);
}
__device__ __forceinline__ uint32_t pack_bf2(float a, float b) {
    __nv_bfloat162 t = __floats2bfloat162_rn(a, b);
    return *reinterpret_cast<uint32_t*>(&t);
}
__device__ __forceinline__ void split_pair(float a, float b, uint32_t& hi, uint32_t& lo) {
    __nv_bfloat16 ah = __float2bfloat16_rn(a);
    __nv_bfloat16 bh = __float2bfloat16_rn(b);
    __nv_bfloat162 hh; hh.x = ah; hh.y = bh;
    hi = *reinterpret_cast<uint32_t*>(&hh);
    lo = pack_bf2(a - __bfloat162float(ah), b - __bfloat162float(bh));
}
__device__ __forceinline__ float bf2sum(uint32_t hw, uint32_t lw, int half) {
    __nv_bfloat162 h = *reinterpret_cast<__nv_bfloat162*>(&hw);
    __nv_bfloat162 l = *reinterpret_cast<__nv_bfloat162*>(&lw);
    return half ? (__bfloat162float(h.y) + __bfloat162float(l.y))
                : (__bfloat162float(h.x) + __bfloat162float(l.x));
}

// ---------------- scratch (device globals) ---------------------------------
__device__ float g_A[BN * NCN * HN * HN];
__device__ __nv_bfloat16 g_qh[MN * HN], g_ql[MN * HN];
__device__ __nv_bfloat16 g_kh[MN * HN], g_kl[MN * HN];
__device__ __nv_bfloat16 g_vh[MN * HN], g_vl[MN * HN];
__device__ __nv_bfloat16 g_Sh[BN * NCN * HN * HN], g_Sl[BN * NCN * HN * HN];
__device__ __nv_bfloat16 g_wt_hi[NPROJ * CN];
__device__ __nv_bfloat16 g_wt_lo[NPROJ * CN];

// ===========================================================================
// Kernel 0: W prep — transpose + split fp32 W[k][n] -> bf16 hi/lo [mat*128+n][k]
// ===========================================================================
__global__ void wprep_kernel(const float* __restrict__ Wq,
                             const float* __restrict__ Wk,
                             const float* __restrict__ Wv)
{
    int k = blockIdx.x;
    int mat = blockIdx.y;
    int n = threadIdx.x;
    const float* W = (mat == 0) ? Wq : (mat == 1) ? Wk : Wv;
    float w = W[(size_t)k * HN + n];
    __nv_bfloat16 hi = __float2bfloat16_rn(w);
    size_t off = ((size_t)mat * HN + n) * CN + k;
    g_wt_hi[off] = hi;
    g_wt_lo[off] = __float2bfloat16_rn(w - __bfloat162float(hi));
}

// ===========================================================================
// Kernel 1: projection GEMM, 256 threads, warp grid 2x4 (64x32 warp tile),
// BK = 64 (128-byte smem rows, ch^(row&7) swizzle), double-buffered.
// ===========================================================================
#define OFF_A_HI 0
#define OFF_A_LO 16384
#define OFF_B_HI 32768
#define OFF_B_LO 49152
#define BUF_SZ 65536
#define NKSTEP (CN / 64)

__global__ __launch_bounds__(256) void proj_mma_kernel(const float* __restrict__ x)
{
    extern __shared__ char sm[];
    const uint32_t sbase = smem_u32(sm);
    const int tid  = threadIdx.x;
    const int wid  = tid >> 5;
    const int lane = tid & 31;
    const int wm   = wid & 1;        // 2 warp-rows (64 M each)
    const int wn   = wid >> 1;       // 4 warp-cols (32 N each)
    const int mat  = blockIdx.x;
    const int m0   = blockIdx.y * 128;
    const int n0   = mat * 128;

    float acc[4][4][4];
#pragma unroll
    for (int a = 0; a < 4; ++a)
#pragma unroll
        for (int b = 0; b < 4; ++b)
#pragma unroll
            for (int c = 0; c < 4; ++c) acc[a][b][c] = 0.0f;

    // per-thread tile units: 128 rows x 8 chunks-of-8-elems = 1024, 4/thread
    // unit u = tid + 256*r : row = u>>3, ch = u&7
    // ---- prologue: LDG A(0) into regs; cp.async B(0) -----------------------
    float4 apre[4][2];
#pragma unroll
    for (int r = 0; r < 4; ++r) {
        int u = tid + 256 * r;
        int row = u >> 3, ch = u & 7;
        const float* src = &x[(size_t)(m0 + row) * CN + ch * 8];
        apre[r][0] = *reinterpret_cast<const float4*>(src);
        apre[r][1] = *reinterpret_cast<const float4*>(src + 4);
    }
#pragma unroll
    for (int r = 0; r < 4; ++r) {
        int u = tid + 256 * r;
        int row = u >> 3, ch = u & 7;
        uint32_t so = (uint32_t)(row * 128 + ((ch ^ (row & 7)) * 16));
        cp16(sbase + OFF_B_HI + so, &g_wt_hi[(size_t)(n0 + row) * CN + ch * 8]);
        cp16(sbase + OFF_B_LO + so, &g_wt_lo[(size_t)(n0 + row) * CN + ch * 8]);
    }
    cp_commit();

    for (int ks = 0; ks < NKSTEP; ++ks) {
        const uint32_t sbuf = sbase + (uint32_t)(ks & 1) * BUF_SZ;
        // ---- split + store A regs into Abuf[cur] --------------------------
#pragma unroll
        for (int r = 0; r < 4; ++r) {
            int u = tid + 256 * r;
            int row = u >> 3, ch = u & 7;
            float f[8] = {apre[r][0].x, apre[r][0].y, apre[r][0].z, apre[r][0].w,
                          apre[r][1].x, apre[r][1].y, apre[r][1].z, apre[r][1].w};
            uint4 vh, vl;
            uint32_t* ph = &vh.x;
            uint32_t* pl = &vl.x;
#pragma unroll
            for (int q = 0; q < 4; ++q) split_pair(f[2*q], f[2*q+1], ph[q], pl[q]);
            uint32_t so = (uint32_t)(row * 128 + ((ch ^ (row & 7)) * 16));
            *reinterpret_cast<uint4*>(sm + (ks & 1) * BUF_SZ + OFF_A_HI + so) = vh;
            *reinterpret_cast<uint4*>(sm + (ks & 1) * BUF_SZ + OFF_A_LO + so) = vl;
        }
        // ---- prefetch next A (LDG) + B (cp.async) -------------------------
        if (ks + 1 < NKSTEP) {
            const int k0n = (ks + 1) * 64;
            const uint32_t snext = sbase + (uint32_t)((ks + 1) & 1) * BUF_SZ;
#pragma unroll
            for (int r = 0; r < 4; ++r) {
                int u = tid + 256 * r;
                int row = u >> 3, ch = u & 7;
                const float* src = &x[(size_t)(m0 + row) * CN + k0n + ch * 8];
                apre[r][0] = *reinterpret_cast<const float4*>(src);
                apre[r][1] = *reinterpret_cast<const float4*>(src + 4);
            }
#pragma unroll
            for (int r = 0; r < 4; ++r) {
                int u = tid + 256 * r;
                int row = u >> 3, ch = u & 7;
                uint32_t so = (uint32_t)(row * 128 + ((ch ^ (row & 7)) * 16));
                cp16(snext + OFF_B_HI + so, &g_wt_hi[(size_t)(n0 + row) * CN + k0n + ch * 8]);
                cp16(snext + OFF_B_LO + so, &g_wt_lo[(size_t)(n0 + row) * CN + k0n + ch * 8]);
            }
            cp_commit();
            asm volatile("cp.async.wait_group 1;" ::: "memory");
        } else {
            asm volatile("cp.async.wait_group 0;" ::: "memory");
        }
        __syncthreads();

        // ---- mma over 4 k16 slices ----------------------------------------
#pragma unroll
        for (int kk = 0; kk < 4; ++kk) {
            uint32_t ah[4][4], al[4][4];
            const int arow = lane & 15;
            const int ach  = kk * 2 + (lane >> 4);
#pragma unroll
            for (int mf = 0; mf < 4; ++mf) {
                int row = wm * 64 + mf * 16 + arow;
                uint32_t so = (uint32_t)(row * 128 + ((ach ^ (row & 7)) * 16));
                ldm_x4(ah[mf], sbuf + OFF_A_HI + so);
                ldm_x4(al[mf], sbuf + OFF_A_LO + so);
            }
            uint32_t bh[2][4], bl[2][4];
            const int brow = (lane & 7) + ((lane >> 4) & 1) * 8;
            const int bch  = kk * 2 + ((lane >> 3) & 1);
#pragma unroll
            for (int nf2 = 0; nf2 < 2; ++nf2) {
                int row = wn * 32 + nf2 * 16 + brow;
                uint32_t so = (uint32_t)(row * 128 + ((bch ^ (row & 7)) * 16));
                ldm_x4(bh[nf2], sbuf + OFF_B_HI + so);
                ldm_x4(bl[nf2], sbuf + OFF_B_LO + so);
            }
#pragma unroll
            for (int mf = 0; mf < 4; ++mf)
#pragma unroll
                for (int nf = 0; nf < 4; ++nf)
                    mma3(acc[mf][nf], ah[mf], al[mf],
                         bh[nf >> 1][(nf & 1) * 2], bh[nf >> 1][(nf & 1) * 2 + 1],
                         bl[nf >> 1][(nf & 1) * 2], bl[nf >> 1][(nf & 1) * 2 + 1]);
        }
        __syncthreads();
    }

    const float sc = (mat == 0) ? SCALE : 1.0f;
    __nv_bfloat16* dsth = (mat == 0) ? g_qh : (mat == 1) ? g_kh : g_vh;
    __nv_bfloat16* dstl = (mat == 0) ? g_ql : (mat == 1) ? g_kl : g_vl;
    const int r0 = lane >> 2;
    const int c0 = (lane & 3) * 2;
#pragma unroll
    for (int mf = 0; mf < 4; ++mf) {
#pragma unroll
        for (int nf = 0; nf < 4; ++nf) {
            int row = m0 + wm * 64 + mf * 16 + r0;
            int col = wn * 32 + nf * 8 + c0;
            float d0 = acc[mf][nf][0] * sc, d1 = acc[mf][nf][1] * sc;
            float d2 = acc[mf][nf][2] * sc, d3 = acc[mf][nf][3] * sc;
            uint32_t h0, l0, h1, l1;
            split_pair(d0, d1, h0, l0);
            split_pair(d2, d3, h1, l1);
            *reinterpret_cast<uint32_t*>(&dsth[(size_t)row * HN + col])       = h0;
            *reinterpret_cast<uint32_t*>(&dstl[(size_t)row * HN + col])       = l0;
            *reinterpret_cast<uint32_t*>(&dsth[(size_t)(row + 8) * HN + col]) = h1;
            *reinterpret_cast<uint32_t*>(&dstl[(size_t)(row + 8) * HN + col]) = l1;
        }
    }
}

// ===========================================================================
// Kernel 2: chunkkv via mma (exact R9 version: 256 threads, 2x4 warp grid)
// ===========================================================================
__global__ __launch_bounds__(256) void chunkkv_mma()
{
    __shared__ __align__(16) char KHI[8192], KLO[8192], VHI[8192], VLO[8192];
    __shared__ float gp[132];

    const int c = blockIdx.x;
    const int b = blockIdx.y;
    const size_t rowbase = (size_t)(b * TN + c * LN);
    const __nv_bfloat16* __restrict__ khp = g_kh + rowbase * HN;
    const __nv_bfloat16* __restrict__ klp = g_kl + rowbase * HN;
    const __nv_bfloat16* __restrict__ vhp = g_vh + rowbase * HN;
    const __nv_bfloat16* __restrict__ vlp = g_vl + rowbase * HN;
    float* __restrict__ ap = g_A + (size_t)(b * NCN + c) * HN * HN;

    const int tid  = threadIdx.x;
    const int wid  = tid >> 5;
    const int lane = tid & 31;
    const int wm   = wid & 1;
    const int wn   = wid >> 1;

    if (tid < 132) gp[tid] = powf(GAMMA, (float)tid);
    const uint32_t skh = smem_u32(KHI), skl = smem_u32(KLO);
    const uint32_t svh = smem_u32(VHI), svl = smem_u32(VLO);
    __syncthreads();

    float acc[4][4][4];
#pragma unroll
    for (int a = 0; a < 4; ++a)
#pragma unroll
        for (int e = 0; e < 4; ++e)
#pragma unroll
            for (int f = 0; f < 4; ++f) acc[a][e][f] = 0.0f;

    for (int jt = 0; jt < 4; ++jt) {
        __syncthreads();
#pragma unroll
        for (int r = 0; r < 2; ++r) {
            int id  = tid + 256 * r;
            int row = id >> 4;
            int ch  = id & 15;
            int j   = jt * 32 + row;
            float w = gp[LN - j];
            uint4 dh = *reinterpret_cast<const uint4*>(&khp[(size_t)j * HN + ch * 8]);
            uint4 dl = *reinterpret_cast<const uint4*>(&klp[(size_t)j * HN + ch * 8]);
            const uint32_t* hw = &dh.x;
            const uint32_t* lw = &dl.x;
            uint4 vh4, vl4;
            uint32_t* ph = &vh4.x;
            uint32_t* pl = &vl4.x;
#pragma unroll
            for (int q = 0; q < 4; ++q) {
                float f0 = bf2sum(hw[q], lw[q], 0) * w;
                float f1 = bf2sum(hw[q], lw[q], 1) * w;
                split_pair(f0, f1, ph[q], pl[q]);
            }
            uint32_t dst = (uint32_t)(row * 256 + ((ch ^ (row & 7)) * 16));
            *reinterpret_cast<uint4*>(KHI + dst) = vh4;
            *reinterpret_cast<uint4*>(KLO + dst) = vl4;
        }
#pragma unroll
        for (int r = 0; r < 2; ++r) {
            int id  = tid + 256 * r;
            int row = id >> 4;
            int ch  = id & 15;
            int j   = jt * 32 + row;
            uint4 dh = *reinterpret_cast<const uint4*>(&vhp[(size_t)j * HN + ch * 8]);
            uint4 dl = *reinterpret_cast<const uint4*>(&vlp[(size_t)j * HN + ch * 8]);
            uint32_t dst = (uint32_t)(row * 256 + ((ch ^ (row & 7)) * 16));
            *reinterpret_cast<uint4*>(VHI + dst) = dh;
            *reinterpret_cast<uint4*>(VLO + dst) = dl;
        }
        __syncthreads();

#pragma unroll
        for (int kk = 0; kk < 2; ++kk) {
            uint32_t ah[4][4], al[4][4];
            const int arow = kk * 16 + (lane & 7) + ((lane >> 4) & 1) * 8;
#pragma unroll
            for (int mf = 0; mf < 4; ++mf) {
                int ach = wm * 8 + mf * 2 + ((lane >> 3) & 1);
                uint32_t so = (uint32_t)(arow * 256 + ((ach ^ (arow & 7)) * 16));
                ldm_x4_t(ah[mf], skh + so);
                ldm_x4_t(al[mf], skl + so);
            }
            uint32_t bh[2][4], bl[2][4];
            const int brow = kk * 16 + (lane & 7) + ((lane >> 3) & 1) * 8;
#pragma unroll
            for (int nf2 = 0; nf2 < 2; ++nf2) {
                int bch = wn * 4 + nf2 * 2 + ((lane >> 4) & 1);
                uint32_t so = (uint32_t)(brow * 256 + ((bch ^ (brow & 7)) * 16));
                ldm_x4_t(bh[nf2], svh + so);
                ldm_x4_t(bl[nf2], svl + so);
            }
#pragma unroll
            for (int mf = 0; mf < 4; ++mf)
#pragma unroll
                for (int nf = 0; nf < 4; ++nf)
                    mma3(acc[mf][nf], ah[mf], al[mf],
                         bh[nf >> 1][(nf & 1) * 2], bh[nf >> 1][(nf & 1) * 2 + 1],
                         bl[nf >> 1][(nf & 1) * 2], bl[nf >> 1][(nf & 1) * 2 + 1]);
        }
    }

    const int r0 = lane >> 2;
    const int c0 = (lane & 3) * 2;
#pragma unroll
    for (int mf = 0; mf < 4; ++mf)
#pragma unroll
        for (int nf = 0; nf < 4; ++nf) {
            int row = wm * 64 + mf * 16 + r0;
            int col = wn * 32 + nf * 8 + c0;
            float2 v0 = {acc[mf][nf][0], acc[mf][nf][1]};
            float2 v1 = {acc[mf][nf][2], acc[mf][nf][3]};
            *reinterpret_cast<float2*>(&ap[(size_t)row * HN + col])       = v0;
            *reinterpret_cast<float2*>(&ap[(size_t)(row + 8) * HN + col]) = v1;
        }
}

// ===========================================================================
// Kernel 3: prefix scan with batched MLP loads (exact R9 version)
// ===========================================================================
__global__ void scan_kernel()
{
    int idx = blockIdx.x * blockDim.x + threadIdx.x;
    if (idx >= BN * HN * HN) return;
    int b = idx / (HN * HN);
    int e = idx % (HN * HN);
    const float gL = powf(GAMMA, (float)LN);
    const size_t base = (size_t)b * NCN * HN * HN + e;

    float a[NCN];
#pragma unroll
    for (int c = 0; c < NCN; ++c)
        a[c] = g_A[base + (size_t)c * HN * HN];

    float S = 0.0f;
#pragma unroll
    for (int c = 0; c < NCN; ++c) {
        size_t off = base + (size_t)c * HN * HN;
        __nv_bfloat16 hi = __float2bfloat16_rn(S);
        g_Sh[off] = hi;
        g_Sl[off] = __float2bfloat16_rn(S - __bfloat162float(hi));
        S = fmaf(S, gL, a[c]);
    }
}

// ===========================================================================
// Kernel 4: out via mma (exact R9 version: 256 threads, fused phase 1 + 2b)
// ===========================================================================
#define OP_HI 0
#define OP_LO 32768
#define OSA   65536
#define OSB   81920
#define OSC   98304
#define OUT_SMEM 114688

__global__ __launch_bounds__(256) void out_mma(float* __restrict__ out)
{
    extern __shared__ char sm[];
    __shared__ float gp[128];
    const uint32_t sb = smem_u32(sm);

    const int c = blockIdx.x;
    const int b = blockIdx.y;
    const size_t rowbase = (size_t)(b * TN + c * LN);
    const __nv_bfloat16* __restrict__ qh = g_qh + rowbase * HN;
    const __nv_bfloat16* __restrict__ ql = g_ql + rowbase * HN;
    const __nv_bfloat16* __restrict__ kh = g_kh + rowbase * HN;
    const __nv_bfloat16* __restrict__ kl = g_kl + rowbase * HN;
    const __nv_bfloat16* __restrict__ vh = g_vh + rowbase * HN;
    const __nv_bfloat16* __restrict__ vl = g_vl + rowbase * HN;
    const __nv_bfloat16* __restrict__ Sh = g_Sh + (size_t)(b * NCN + c) * HN * HN;
    const __nv_bfloat16* __restrict__ Sl = g_Sl + (size_t)(b * NCN + c) * HN * HN;

    const int tid  = threadIdx.x;
    const int wid  = tid >> 5;
    const int lane = tid & 31;
    const int wm   = wid & 1;
    const int wn   = wid >> 1;

    if (tid < 128) gp[tid] = powf(GAMMA, (float)tid);
    __syncthreads();

    auto copy128x32 = [&](int dstOff, const __nv_bfloat16* src, int h0) {
#pragma unroll
        for (int r = 0; r < 2; ++r) {
            int id  = tid + 256 * r;
            int row = id >> 2;
            int ch  = id & 3;
            uint4 d = *reinterpret_cast<const uint4*>(&src[(size_t)row * HN + h0 + ch * 8]);
            *reinterpret_cast<uint4*>(sm + dstOff + row * 64 +
                                      ((ch ^ ((row >> 1) & 3)) * 16)) = d;
        }
    };
    auto copy32x128 = [&](int dstOff, const __nv_bfloat16* src) {
#pragma unroll
        for (int r = 0; r < 2; ++r) {
            int id  = tid + 256 * r;
            int row = id >> 4;
            int ch  = id & 15;
            uint4 d = *reinterpret_cast<const uint4*>(&src[(size_t)row * HN + ch * 8]);
            *reinterpret_cast<uint4*>(sm + dstOff + row * 256 +
                                      ((ch ^ (row & 7)) * 16)) = d;
        }
    };

    // ---------------- fused phase 1 + 2b: P = Q K^T, O = Q S ---------------
    float pAcc[4][4][4], oAcc[4][4][4];
#pragma unroll
    for (int a = 0; a < 4; ++a)
#pragma unroll
        for (int e = 0; e < 4; ++e)
#pragma unroll
            for (int f = 0; f < 4; ++f) { pAcc[a][e][f] = 0.0f; oAcc[a][e][f] = 0.0f; }

    const bool p1skip = (wm == 0 && wn >= 2);
    for (int ks = 0; ks < 4; ++ks) {
        __syncthreads();
        copy128x32(OSA,        qh, ks * 32);
        copy128x32(OSA + 8192, ql, ks * 32);
        copy128x32(OSB,        kh, ks * 32);
        copy128x32(OSB + 8192, kl, ks * 32);
        copy32x128(OSC,        Sh + (size_t)ks * 32 * HN);
        copy32x128(OSC + 8192, Sl + (size_t)ks * 32 * HN);
        __syncthreads();
#pragma unroll
        for (int kk = 0; kk < 2; ++kk) {
            uint32_t ah[4][4], al[4][4];
            const int arow = lane & 15;
            const int ach  = kk * 2 + (lane >> 4);
#pragma unroll
            for (int mf = 0; mf < 4; ++mf) {
                int row = wm * 64 + mf * 16 + arow;
                uint32_t so = (uint32_t)(row * 64 + ((ach ^ ((row >> 1) & 3)) * 16));
                ldm_x4(ah[mf], sb + OSA + so);
                ldm_x4(al[mf], sb + OSA + 8192 + so);
            }
            if (!p1skip) {
                uint32_t bh[2][4], bl[2][4];
                const int brow = (lane & 7) + ((lane >> 4) & 1) * 8;
                const int bch  = kk * 2 + ((lane >> 3) & 1);
#pragma unroll
                for (int nf2 = 0; nf2 < 2; ++nf2) {
                    int row = wn * 32 + nf2 * 16 + brow;
                    uint32_t so = (uint32_t)(row * 64 + ((bch ^ ((row >> 1) & 3)) * 16));
                    ldm_x4(bh[nf2], sb + OSB + so);
                    ldm_x4(bl[nf2], sb + OSB + 8192 + so);
                }
#pragma unroll
                for (int mf = 0; mf < 4; ++mf)
#pragma unroll
                    for (int nf = 0; nf < 4; ++nf)
                        mma3(pAcc[mf][nf], ah[mf], al[mf],
                             bh[nf >> 1][(nf & 1) * 2], bh[nf >> 1][(nf & 1) * 2 + 1],
                             bl[nf >> 1][(nf & 1) * 2], bl[nf >> 1][(nf & 1) * 2 + 1]);
            }
            {
                uint32_t bh[2][4], bl[2][4];
                const int brow = kk * 16 + (lane & 7) + ((lane >> 3) & 1) * 8;
#pragma unroll
                for (int nf2 = 0; nf2 < 2; ++nf2) {
                    int bch = wn * 4 + nf2 * 2 + ((lane >> 4) & 1);
                    uint32_t so = (uint32_t)(brow * 256 + ((bch ^ (brow & 7)) * 16));
                    ldm_x4_t(bh[nf2], sb + OSC + so);
                    ldm_x4_t(bl[nf2], sb + OSC + 8192 + so);
                }
#pragma unroll
                for (int mf = 0; mf < 4; ++mf)
#pragma unroll
                    for (int nf = 0; nf < 4; ++nf)
                        mma3(oAcc[mf][nf], ah[mf], al[mf],
                             bh[nf >> 1][(nf & 1) * 2], bh[nf >> 1][(nf & 1) * 2 + 1],
                             bl[nf >> 1][(nf & 1) * 2], bl[nf >> 1][(nf & 1) * 2 + 1]);
            }
        }
    }

    // ---------------- mask + split + store P to smem; scale O --------------
    {
        const int r0 = lane >> 2;
        const int c0 = (lane & 3) * 2;
#pragma unroll
        for (int mf = 0; mf < 4; ++mf) {
            int i0 = wm * 64 + mf * 16 + r0;
            int i1 = i0 + 8;
            float g0 = gp[i0], g1 = gp[i1];
#pragma unroll
            for (int nf = 0; nf < 4; ++nf) {
                int j0 = wn * 32 + nf * 8 + c0;
                int j1 = j0 + 1;
                float d0 = (i0 >= j0) ? pAcc[mf][nf][0] * gp[i0 - j0] : 0.0f;
                float d1 = (i0 >= j1) ? pAcc[mf][nf][1] * gp[i0 - j1] : 0.0f;
                float d2 = (i1 >= j0) ? pAcc[mf][nf][2] * gp[i1 - j0] : 0.0f;
                float d3 = (i1 >= j1) ? pAcc[mf][nf][3] * gp[i1 - j1] : 0.0f;
                uint32_t h0, l0, h1, l1;
                split_pair(d0, d1, h0, l0);
                split_pair(d2, d3, h1, l1);
                uint32_t a0 = (uint32_t)(i0 * 256 + (((j0 >> 3) ^ (i0 & 7)) * 16) + (j0 & 7) * 2);
                uint32_t a1 = (uint32_t)(i1 * 256 + (((j0 >> 3) ^ (i1 & 7)) * 16) + (j0 & 7) * 2);
                *reinterpret_cast<uint32_t*>(sm + OP_HI + a0) = h0;
                *reinterpret_cast<uint32_t*>(sm + OP_LO + a0) = l0;
                *reinterpret_cast<uint32_t*>(sm + OP_HI + a1) = h1;
                *reinterpret_cast<uint32_t*>(sm + OP_LO + a1) = l1;
                oAcc[mf][nf][0] *= g0;
                oAcc[mf][nf][1] *= g0;
                oAcc[mf][nf][2] *= g1;
                oAcc[mf][nf][3] *= g1;
            }
        }
    }

    // ---------------- phase 2a: O += P @ V ---------------------------------
    for (int jt = 0; jt < 4; ++jt) {
        __syncthreads();
        copy32x128(OSB,        vh + (size_t)jt * 32 * HN);
        copy32x128(OSB + 8192, vl + (size_t)jt * 32 * HN);
        __syncthreads();
        if (wm == 0 && jt >= 2) continue;
#pragma unroll
        for (int kk = 0; kk < 2; ++kk) {
            const int ks = jt * 2 + kk;
            uint32_t ah[4][4], al[4][4];
            const int arow = lane & 15;
            const int ach  = ks * 2 + (lane >> 4);
#pragma unroll
            for (int mf = 0; mf < 4; ++mf) {
                int row = wm * 64 + mf * 16 + arow;
                uint32_t so = (uint32_t)(row * 256 + ((ach ^ (row & 7)) * 16));
                ldm_x4(ah[mf], sb + OP_HI + so);
                ldm_x4(al[mf], sb + OP_LO + so);
            }
            uint32_t bh[2][4], bl[2][4];
            const int brow = kk * 16 + (lane & 7) + ((lane >> 3) & 1) * 8;
#pragma unroll
            for (int nf2 = 0; nf2 < 2; ++nf2) {
                int bch = wn * 4 + nf2 * 2 + ((lane >> 4) & 1);
                uint32_t so = (uint32_t)(brow * 256 + ((bch ^ (brow & 7)) * 16));
                ldm_x4_t(bh[nf2], sb + OSB + so);
                ldm_x4_t(bl[nf2], sb + OSB + 8192 + so);
            }
#pragma unroll
            for (int mf = 0; mf < 4; ++mf)
#pragma unroll
                for (int nf = 0; nf < 4; ++nf)
                    mma3(oAcc[mf][nf], ah[mf], al[mf],
                         bh[nf >> 1][(nf & 1) * 2], bh[nf >> 1][(nf & 1) * 2 + 1],
                         bl[nf >> 1][(nf & 1) * 2], bl[nf >> 1][(nf & 1) * 2 + 1]);
        }
    }

    // ---------------- store O ----------------------------------------------
    {
        const int r0 = lane >> 2;
        const int c0 = (lane & 3) * 2;
#pragma unroll
        for (int mf = 0; mf < 4; ++mf)
#pragma unroll
            for (int nf = 0; nf < 4; ++nf) {
                size_t row = rowbase + wm * 64 + mf * 16 + r0;
                int col = wn * 32 + nf * 8 + c0;
                float2 v0 = {oAcc[mf][nf][0], oAcc[mf][nf][1]};
                float2 v1 = {oAcc[mf][nf][2], oAcc[mf][nf][3]};
                *reinterpret_cast<float2*>(&out[row * HN + col])       = v0;
                *reinterpret_cast<float2*>(&out[(row + 8) * HN + col]) = v1;
            }
    }
}

// ===========================================================================
extern "C" void kernel_launch(void* const* d_in, const int* in_sizes, int n_in,
                              void* d_out, int out_size)
{
    const float* x  = (const float*)d_in[0];
    const float* Wq = (const float*)d_in[1];
    const float* Wk = (const float*)d_in[2];
    const float* Wv = (const float*)d_in[3];
    float* out = (float*)d_out;

    cudaFuncSetAttribute(proj_mma_kernel, cudaFuncAttributeMaxDynamicSharedMemorySize,
                         2 * BUF_SZ);
    cudaFuncSetAttribute(out_mma, cudaFuncAttributeMaxDynamicSharedMemorySize,
                         OUT_SMEM);

    wprep_kernel<<<dim3(CN, 3), HN>>>(Wq, Wk, Wv);
    proj_mma_kernel<<<dim3(3, MN / 128), 256, 2 * BUF_SZ>>>(x);
    chunkkv_mma<<<dim3(NCN, BN), 256>>>();
    scan_kernel<<<(BN * HN * HN + 255) / 256, 256>>>();
    out_mma<<<dim3(NCN, BN), 256, OUT_SMEM>>>(out);
}

// round 15
// speedup vs baseline: 1.1676x; 1.0584x over previous
#include <cuda_runtime.h>
#include <cuda_bf16.h>
#include <math.h>
#include <stdint.h>

// Problem constants: RetentionHead  B=4, T=4096, C=1024, H=128
#define BN 4
#define TN 4096
#define CN 1024
#define HN 128
#define LN 128
#define NCN (TN / LN)          // 32 chunks per batch
#define MN (BN * TN)           // 16384 rows
#define NPROJ 384
#define GAMMA 0.96875f
#define SCALE 0.03125f         // C^-0.5

typedef unsigned long long ull;

// ---------------- mma.sync / ldmatrix / cp.async helpers -------------------
__device__ __forceinline__ uint32_t smem_u32(const void* p) {
    uint32_t a;
    asm("{ .reg .u64 t; cvta.to.shared.u64 t, %1; cvt.u32.u64 %0, t; }" : "=r"(a) : "l"(p));
    return a;
}
__device__ __forceinline__ void cp16(uint32_t s, const void* g) {
    asm volatile("cp.async.cg.shared.global [%0], [%1], 16;" :: "r"(s), "l"(g));
}
__device__ __forceinline__ void cp_commit() {
    asm volatile("cp.async.commit_group;" ::: "memory");
}
__device__ __forceinline__ void ldm_x4(uint32_t* r, uint32_t addr) {
    asm volatile("ldmatrix.sync.aligned.m8n8.x4.shared.b16 {%0,%1,%2,%3}, [%4];"
                 : "=r"(r[0]), "=r"(r[1]), "=r"(r[2]), "=r"(r[3]) : "r"(addr));
}
__device__ __forceinline__ void ldm_x4_t(uint32_t* r, uint32_t addr) {
    asm volatile("ldmatrix.sync.aligned.m8n8.x4.trans.shared.b16 {%0,%1,%2,%3}, [%4];"
                 : "=r"(r[0]), "=r"(r[1]), "=r"(r[2]), "=r"(r[3]) : "r"(addr));
}
__device__ __forceinline__ void mma_bf16(float* d, const uint32_t* a,
                                         uint32_t b0, uint32_t b1) {
    asm volatile(
        "mma.sync.aligned.m16n8k16.row.col.f32.bf16.bf16.f32 "
        "{%0,%1,%2,%3}, {%4,%5,%6,%7}, {%8,%9}, {%0,%1,%2,%3};"
        : "+f"(d[0]), "+f"(d[1]), "+f"(d[2]), "+f"(d[3])
        : "r"(a[0]), "r"(a[1]), "r"(a[2]), "r"(a[3]), "r"(b0), "r"(b1));
}
// 3-product split-2 mma: hi*hi + lo*hi + hi*lo
__device__ __forceinline__ void mma3(float* d, const uint32_t* ah, const uint32_t* al,
                                     uint32_t bh0, uint32_t bh1,
                                     uint32_t bl0, uint32_t bl1) {
    mma_bf16(d, ah, bh0, bh1);
    mma_bf16(d, al, bh0, bh1);
    mma_bf16(d, ah, bl0, bl1);
}
__device__ __forceinline__ uint32_t pack_bf2(float a, float b) {
    __nv_bfloat162 t = __floats2bfloat162_rn(a, b);
    return *reinterpret_cast<uint32_t*>(&t);
}
__device__ __forceinline__ void split_pair(float a, float b, uint32_t& hi, uint32_t& lo) {
    __nv_bfloat16 ah = __float2bfloat16_rn(a);
    __nv_bfloat16 bh = __float2bfloat16_rn(b);
    __nv_bfloat162 hh; hh.x = ah; hh.y = bh;
    hi = *reinterpret_cast<uint32_t*>(&hh);
    lo = pack_bf2(a - __bfloat162float(ah), b - __bfloat162float(bh));
}
__device__ __forceinline__ float bf2sum(uint32_t hw, uint32_t lw, int half) {
    __nv_bfloat162 h = *reinterpret_cast<__nv_bfloat162*>(&hw);
    __nv_bfloat162 l = *reinterpret_cast<__nv_bfloat162*>(&lw);
    return half ? (__bfloat162float(h.y) + __bfloat162float(l.y))
                : (__bfloat162float(h.x) + __bfloat162float(l.x));
}

// ---------------- scratch (device globals) ---------------------------------
__device__ float g_A[BN * NCN * HN * HN];
__device__ __nv_bfloat16 g_qh[MN * HN], g_ql[MN * HN];
__device__ __nv_bfloat16 g_kh[MN * HN], g_kl[MN * HN];
__device__ __nv_bfloat16 g_vh[MN * HN], g_vl[MN * HN];
__device__ __nv_bfloat16 g_Sh[BN * NCN * HN * HN], g_Sl[BN * NCN * HN * HN];
__device__ __nv_bfloat16 g_wt_hi[NPROJ * CN];
__device__ __nv_bfloat16 g_wt_lo[NPROJ * CN];

// ===========================================================================
// Kernel 0: W prep — transpose + split fp32 W[k][n] -> bf16 hi/lo [mat*128+n][k]
// ===========================================================================
__global__ void wprep_kernel(const float* __restrict__ Wq,
                             const float* __restrict__ Wk,
                             const float* __restrict__ Wv)
{
    int k = blockIdx.x;
    int mat = blockIdx.y;
    int n = threadIdx.x;
    const float* W = (mat == 0) ? Wq : (mat == 1) ? Wk : Wv;
    float w = W[(size_t)k * HN + n];
    __nv_bfloat16 hi = __float2bfloat16_rn(w);
    size_t off = ((size_t)mat * HN + n) * CN + k;
    g_wt_hi[off] = hi;
    g_wt_lo[off] = __float2bfloat16_rn(w - __bfloat162float(hi));
}

// ===========================================================================
// Kernel 1: projection GEMM via mma.sync bf16 split-2, fp32 x split fused.
// ===========================================================================
#define OFF_A_HI 0
#define OFF_A_LO 8192
#define OFF_B_HI 16384
#define OFF_B_LO 24576
#define BUF_SZ 32768
#define NKSTEP (CN / 32)

__global__ __launch_bounds__(256) void proj_mma_kernel(const float* __restrict__ x)
{
    extern __shared__ char sm[];
    const uint32_t sbase = smem_u32(sm);
    const int tid  = threadIdx.x;
    const int wid  = tid >> 5;
    const int lane = tid & 31;
    const int wm   = wid & 1;
    const int wn   = wid >> 1;
    const int mat  = blockIdx.x;
    const int m0   = blockIdx.y * 128;
    const int n0   = mat * 128;

    const int arow0 = tid >> 2;
    const int ach0  = tid & 3;

    float acc[4][4][4];
#pragma unroll
    for (int a = 0; a < 4; ++a)
#pragma unroll
        for (int b = 0; b < 4; ++b)
#pragma unroll
            for (int c = 0; c < 4; ++c) acc[a][b][c] = 0.0f;

    float4 apre[2][2];
#pragma unroll
    for (int r = 0; r < 2; ++r) {
        int row = arow0 + 64 * r;
        const float* src = &x[(size_t)(m0 + row) * CN + ach0 * 8];
        apre[r][0] = *reinterpret_cast<const float4*>(src);
        apre[r][1] = *reinterpret_cast<const float4*>(src + 4);
    }
#pragma unroll
    for (int r = 0; r < 2; ++r) {
        int row = arow0 + 64 * r;
        uint32_t so = (uint32_t)(row * 64 + ((ach0 ^ ((row >> 1) & 3)) * 16));
        cp16(sbase + OFF_B_HI + so, &g_wt_hi[(size_t)(n0 + row) * CN + ach0 * 8]);
        cp16(sbase + OFF_B_LO + so, &g_wt_lo[(size_t)(n0 + row) * CN + ach0 * 8]);
    }
    cp_commit();

    for (int ks = 0; ks < NKSTEP; ++ks) {
        const uint32_t sbuf = sbase + (uint32_t)(ks & 1) * BUF_SZ;
        {
#pragma unroll
            for (int r = 0; r < 2; ++r) {
                int row = arow0 + 64 * r;
                float f[8] = {apre[r][0].x, apre[r][0].y, apre[r][0].z, apre[r][0].w,
                              apre[r][1].x, apre[r][1].y, apre[r][1].z, apre[r][1].w};
                uint4 vh, vl;
                uint32_t* ph = &vh.x;
                uint32_t* pl = &vl.x;
#pragma unroll
                for (int q = 0; q < 4; ++q) split_pair(f[2*q], f[2*q+1], ph[q], pl[q]);
                uint32_t so = (uint32_t)(row * 64 + ((ach0 ^ ((row >> 1) & 3)) * 16));
                *reinterpret_cast<uint4*>(sm + (ks & 1) * BUF_SZ + OFF_A_HI + so) = vh;
                *reinterpret_cast<uint4*>(sm + (ks & 1) * BUF_SZ + OFF_A_LO + so) = vl;
            }
        }
        if (ks + 1 < NKSTEP) {
            const int k0n = (ks + 1) * 32;
            const uint32_t snext = sbase + (uint32_t)((ks + 1) & 1) * BUF_SZ;
#pragma unroll
            for (int r = 0; r < 2; ++r) {
                int row = arow0 + 64 * r;
                const float* src = &x[(size_t)(m0 + row) * CN + k0n + ach0 * 8];
                apre[r][0] = *reinterpret_cast<const float4*>(src);
                apre[r][1] = *reinterpret_cast<const float4*>(src + 4);
            }
#pragma unroll
            for (int r = 0; r < 2; ++r) {
                int row = arow0 + 64 * r;
                uint32_t so = (uint32_t)(row * 64 + ((ach0 ^ ((row >> 1) & 3)) * 16));
                cp16(snext + OFF_B_HI + so, &g_wt_hi[(size_t)(n0 + row) * CN + k0n + ach0 * 8]);
                cp16(snext + OFF_B_LO + so, &g_wt_lo[(size_t)(n0 + row) * CN + k0n + ach0 * 8]);
            }
            cp_commit();
            asm volatile("cp.async.wait_group 1;" ::: "memory");
        } else {
            asm volatile("cp.async.wait_group 0;" ::: "memory");
        }
        __syncthreads();

#pragma unroll
        for (int kk = 0; kk < 2; ++kk) {
            uint32_t ah[4][4], al[4][4];
            const int arow = lane & 15;
            const int ach  = kk * 2 + (lane >> 4);
#pragma unroll
            for (int mf = 0; mf < 4; ++mf) {
                int row = wm * 64 + mf * 16 + arow;
                uint32_t so = (uint32_t)(row * 64 + ((ach ^ ((row >> 1) & 3)) * 16));
                ldm_x4(ah[mf], sbuf + OFF_A_HI + so);
                ldm_x4(al[mf], sbuf + OFF_A_LO + so);
            }
            uint32_t bh[2][4], bl[2][4];
            const int brow = (lane & 7) + ((lane >> 4) & 1) * 8;
            const int bch  = kk * 2 + ((lane >> 3) & 1);
#pragma unroll
            for (int nf2 = 0; nf2 < 2; ++nf2) {
                int row = wn * 32 + nf2 * 16 + brow;
                uint32_t so = (uint32_t)(row * 64 + ((bch ^ ((row >> 1) & 3)) * 16));
                ldm_x4(bh[nf2], sbuf + OFF_B_HI + so);
                ldm_x4(bl[nf2], sbuf + OFF_B_LO + so);
            }
#pragma unroll
            for (int mf = 0; mf < 4; ++mf)
#pragma unroll
                for (int nf = 0; nf < 4; ++nf)
                    mma3(acc[mf][nf], ah[mf], al[mf],
                         bh[nf >> 1][(nf & 1) * 2], bh[nf >> 1][(nf & 1) * 2 + 1],
                         bl[nf >> 1][(nf & 1) * 2], bl[nf >> 1][(nf & 1) * 2 + 1]);
        }
        __syncthreads();
    }

    const float sc = (mat == 0) ? SCALE : 1.0f;
    __nv_bfloat16* dsth = (mat == 0) ? g_qh : (mat == 1) ? g_kh : g_vh;
    __nv_bfloat16* dstl = (mat == 0) ? g_ql : (mat == 1) ? g_kl : g_vl;
    const int r0 = lane >> 2;
    const int c0 = (lane & 3) * 2;
#pragma unroll
    for (int mf = 0; mf < 4; ++mf) {
#pragma unroll
        for (int nf = 0; nf < 4; ++nf) {
            int row = m0 + wm * 64 + mf * 16 + r0;
            int col = wn * 32 + nf * 8 + c0;
            float d0 = acc[mf][nf][0] * sc, d1 = acc[mf][nf][1] * sc;
            float d2 = acc[mf][nf][2] * sc, d3 = acc[mf][nf][3] * sc;
            uint32_t h0, l0, h1, l1;
            split_pair(d0, d1, h0, l0);
            split_pair(d2, d3, h1, l1);
            *reinterpret_cast<uint32_t*>(&dsth[(size_t)row * HN + col])       = h0;
            *reinterpret_cast<uint32_t*>(&dstl[(size_t)row * HN + col])       = l0;
            *reinterpret_cast<uint32_t*>(&dsth[(size_t)(row + 8) * HN + col]) = h1;
            *reinterpret_cast<uint32_t*>(&dstl[(size_t)(row + 8) * HN + col]) = l1;
        }
    }
}

// ===========================================================================
// Kernel 2: chunkkv via mma
// ===========================================================================
__global__ __launch_bounds__(256) void chunkkv_mma()
{
    __shared__ __align__(16) char KHI[8192], KLO[8192], VHI[8192], VLO[8192];
    __shared__ float gp[132];

    const int c = blockIdx.x;
    const int b = blockIdx.y;
    const size_t rowbase = (size_t)(b * TN + c * LN);
    const __nv_bfloat16* __restrict__ khp = g_kh + rowbase * HN;
    const __nv_bfloat16* __restrict__ klp = g_kl + rowbase * HN;
    const __nv_bfloat16* __restrict__ vhp = g_vh + rowbase * HN;
    const __nv_bfloat16* __restrict__ vlp = g_vl + rowbase * HN;
    float* __restrict__ ap = g_A + (size_t)(b * NCN + c) * HN * HN;

    const int tid  = threadIdx.x;
    const int wid  = tid >> 5;
    const int lane = tid & 31;
    const int wm   = wid & 1;
    const int wn   = wid >> 1;

    if (tid < 132) gp[tid] = powf(GAMMA, (float)tid);
    const uint32_t skh = smem_u32(KHI), skl = smem_u32(KLO);
    const uint32_t svh = smem_u32(VHI), svl = smem_u32(VLO);
    __syncthreads();

    float acc[4][4][4];
#pragma unroll
    for (int a = 0; a < 4; ++a)
#pragma unroll
        for (int e = 0; e < 4; ++e)
#pragma unroll
            for (int f = 0; f < 4; ++f) acc[a][e][f] = 0.0f;

    for (int jt = 0; jt < 4; ++jt) {
        __syncthreads();
#pragma unroll
        for (int r = 0; r < 2; ++r) {
            int id  = tid + 256 * r;
            int row = id >> 4;
            int ch  = id & 15;
            int j   = jt * 32 + row;
            float w = gp[LN - j];
            uint4 dh = *reinterpret_cast<const uint4*>(&khp[(size_t)j * HN + ch * 8]);
            uint4 dl = *reinterpret_cast<const uint4*>(&klp[(size_t)j * HN + ch * 8]);
            const uint32_t* hw = &dh.x;
            const uint32_t* lw = &dl.x;
            uint4 vh4, vl4;
            uint32_t* ph = &vh4.x;
            uint32_t* pl = &vl4.x;
#pragma unroll
            for (int q = 0; q < 4; ++q) {
                float f0 = bf2sum(hw[q], lw[q], 0) * w;
                float f1 = bf2sum(hw[q], lw[q], 1) * w;
                split_pair(f0, f1, ph[q], pl[q]);
            }
            uint32_t dst = (uint32_t)(row * 256 + ((ch ^ (row & 7)) * 16));
            *reinterpret_cast<uint4*>(KHI + dst) = vh4;
            *reinterpret_cast<uint4*>(KLO + dst) = vl4;
        }
#pragma unroll
        for (int r = 0; r < 2; ++r) {
            int id  = tid + 256 * r;
            int row = id >> 4;
            int ch  = id & 15;
            int j   = jt * 32 + row;
            uint4 dh = *reinterpret_cast<const uint4*>(&vhp[(size_t)j * HN + ch * 8]);
            uint4 dl = *reinterpret_cast<const uint4*>(&vlp[(size_t)j * HN + ch * 8]);
            uint32_t dst = (uint32_t)(row * 256 + ((ch ^ (row & 7)) * 16));
            *reinterpret_cast<uint4*>(VHI + dst) = dh;
            *reinterpret_cast<uint4*>(VLO + dst) = dl;
        }
        __syncthreads();

#pragma unroll
        for (int kk = 0; kk < 2; ++kk) {
            uint32_t ah[4][4], al[4][4];
            const int arow = kk * 16 + (lane & 7) + ((lane >> 4) & 1) * 8;
#pragma unroll
            for (int mf = 0; mf < 4; ++mf) {
                int ach = wm * 8 + mf * 2 + ((lane >> 3) & 1);
                uint32_t so = (uint32_t)(arow * 256 + ((ach ^ (arow & 7)) * 16));
                ldm_x4_t(ah[mf], skh + so);
                ldm_x4_t(al[mf], skl + so);
            }
            uint32_t bh[2][4], bl[2][4];
            const int brow = kk * 16 + (lane & 7) + ((lane >> 3) & 1) * 8;
#pragma unroll
            for (int nf2 = 0; nf2 < 2; ++nf2) {
                int bch = wn * 4 + nf2 * 2 + ((lane >> 4) & 1);
                uint32_t so = (uint32_t)(brow * 256 + ((bch ^ (brow & 7)) * 16));
                ldm_x4_t(bh[nf2], svh + so);
                ldm_x4_t(bl[nf2], svl + so);
            }
#pragma unroll
            for (int mf = 0; mf < 4; ++mf)
#pragma unroll
                for (int nf = 0; nf < 4; ++nf)
                    mma3(acc[mf][nf], ah[mf], al[mf],
                         bh[nf >> 1][(nf & 1) * 2], bh[nf >> 1][(nf & 1) * 2 + 1],
                         bl[nf >> 1][(nf & 1) * 2], bl[nf >> 1][(nf & 1) * 2 + 1]);
        }
    }

    const int r0 = lane >> 2;
    const int c0 = (lane & 3) * 2;
#pragma unroll
    for (int mf = 0; mf < 4; ++mf)
#pragma unroll
        for (int nf = 0; nf < 4; ++nf) {
            int row = wm * 64 + mf * 16 + r0;
            int col = wn * 32 + nf * 8 + c0;
            float2 v0 = {acc[mf][nf][0], acc[mf][nf][1]};
            float2 v1 = {acc[mf][nf][2], acc[mf][nf][3]};
            *reinterpret_cast<float2*>(&ap[(size_t)row * HN + col])       = v0;
            *reinterpret_cast<float2*>(&ap[(size_t)(row + 8) * HN + col]) = v1;
        }
}

// ===========================================================================
// Kernel 3: prefix scan with batched MLP loads
// ===========================================================================
__global__ void scan_kernel()
{
    int idx = blockIdx.x * blockDim.x + threadIdx.x;
    if (idx >= BN * HN * HN) return;
    int b = idx / (HN * HN);
    int e = idx % (HN * HN);
    const float gL = powf(GAMMA, (float)LN);
    const size_t base = (size_t)b * NCN * HN * HN + e;

    float a[NCN];
#pragma unroll
    for (int c = 0; c < NCN; ++c)
        a[c] = g_A[base + (size_t)c * HN * HN];

    float S = 0.0f;
#pragma unroll
    for (int c = 0; c < NCN; ++c) {
        size_t off = base + (size_t)c * HN * HN;
        __nv_bfloat16 hi = __float2bfloat16_rn(S);
        g_Sh[off] = hi;
        g_Sl[off] = __float2bfloat16_rn(S - __bfloat162float(hi));
        S = fmaf(S, gL, a[c]);
    }
}

// ===========================================================================
// Kernel 4: out via mma (256 threads, fused phase 1 + 2b)
// ===========================================================================
#define OP_HI 0
#define OP_LO 32768
#define OSA   65536
#define OSB   81920
#define OSC   98304
#define OUT_SMEM 114688

__global__ __launch_bounds__(256) void out_mma(float* __restrict__ out)
{
    extern __shared__ char sm[];
    __shared__ float gp[128];
    const uint32_t sb = smem_u32(sm);

    const int c = blockIdx.x;
    const int b = blockIdx.y;
    const size_t rowbase = (size_t)(b * TN + c * LN);
    const __nv_bfloat16* __restrict__ qh = g_qh + rowbase * HN;
    const __nv_bfloat16* __restrict__ ql = g_ql + rowbase * HN;
    const __nv_bfloat16* __restrict__ kh = g_kh + rowbase * HN;
    const __nv_bfloat16* __restrict__ kl = g_kl + rowbase * HN;
    const __nv_bfloat16* __restrict__ vh = g_vh + rowbase * HN;
    const __nv_bfloat16* __restrict__ vl = g_vl + rowbase * HN;
    const __nv_bfloat16* __restrict__ Sh = g_Sh + (size_t)(b * NCN + c) * HN * HN;
    const __nv_bfloat16* __restrict__ Sl = g_Sl + (size_t)(b * NCN + c) * HN * HN;

    const int tid  = threadIdx.x;
    const int wid  = tid >> 5;
    const int lane = tid & 31;
    const int wm   = wid & 1;
    const int wn   = wid >> 1;

    if (tid < 128) gp[tid] = powf(GAMMA, (float)tid);
    __syncthreads();

    auto copy128x32 = [&](int dstOff, const __nv_bfloat16* src, int h0) {
#pragma unroll
        for (int r = 0; r < 2; ++r) {
            int id  = tid + 256 * r;
            int row = id >> 2;
            int ch  = id & 3;
            uint4 d = *reinterpret_cast<const uint4*>(&src[(size_t)row * HN + h0 + ch * 8]);
            *reinterpret_cast<uint4*>(sm + dstOff + row * 64 +
                                      ((ch ^ ((row >> 1) & 3)) * 16)) = d;
        }
    };
    auto copy32x128 = [&](int dstOff, const __nv_bfloat16* src) {
#pragma unroll
        for (int r = 0; r < 2; ++r) {
            int id  = tid + 256 * r;
            int row = id >> 4;
            int ch  = id & 15;
            uint4 d = *reinterpret_cast<const uint4*>(&src[(size_t)row * HN + ch * 8]);
            *reinterpret_cast<uint4*>(sm + dstOff + row * 256 +
                                      ((ch ^ (row & 7)) * 16)) = d;
        }
    };

    float pAcc[4][4][4], oAcc[4][4][4];
#pragma unroll
    for (int a = 0; a < 4; ++a)
#pragma unroll
        for (int e = 0; e < 4; ++e)
#pragma unroll
            for (int f = 0; f < 4; ++f) { pAcc[a][e][f] = 0.0f; oAcc[a][e][f] = 0.0f; }

    const bool p1skip = (wm == 0 && wn >= 2);
    for (int ks = 0; ks < 4; ++ks) {
        __syncthreads();
        copy128x32(OSA,        qh, ks * 32);
        copy128x32(OSA + 8192, ql, ks * 32);
        copy128x32(OSB,        kh, ks * 32);
        copy128x32(OSB + 8192, kl, ks * 32);
        copy32x128(OSC,        Sh + (size_t)ks * 32 * HN);
        copy32x128(OSC + 8192, Sl + (size_t)ks * 32 * HN);
        __syncthreads();
#pragma unroll
        for (int kk = 0; kk < 2; ++kk) {
            uint32_t ah[4][4], al[4][4];
            const int arow = lane & 15;
            const int ach  = kk * 2 + (lane >> 4);
#pragma unroll
            for (int mf = 0; mf < 4; ++mf) {
                int row = wm * 64 + mf * 16 + arow;
                uint32_t so = (uint32_t)(row * 64 + ((ach ^ ((row >> 1) & 3)) * 16));
                ldm_x4(ah[mf], sb + OSA + so);
                ldm_x4(al[mf], sb + OSA + 8192 + so);
            }
            if (!p1skip) {
                uint32_t bh[2][4], bl[2][4];
                const int brow = (lane & 7) + ((lane >> 4) & 1) * 8;
                const int bch  = kk * 2 + ((lane >> 3) & 1);
#pragma unroll
                for (int nf2 = 0; nf2 < 2; ++nf2) {
                    int row = wn * 32 + nf2 * 16 + brow;
                    uint32_t so = (uint32_t)(row * 64 + ((bch ^ ((row >> 1) & 3)) * 16));
                    ldm_x4(bh[nf2], sb + OSB + so);
                    ldm_x4(bl[nf2], sb + OSB + 8192 + so);
                }
#pragma unroll
                for (int mf = 0; mf < 4; ++mf)
#pragma unroll
                    for (int nf = 0; nf < 4; ++nf)
                        mma3(pAcc[mf][nf], ah[mf], al[mf],
                             bh[nf >> 1][(nf & 1) * 2], bh[nf >> 1][(nf & 1) * 2 + 1],
                             bl[nf >> 1][(nf & 1) * 2], bl[nf >> 1][(nf & 1) * 2 + 1]);
            }
            {
                uint32_t bh[2][4], bl[2][4];
                const int brow = kk * 16 + (lane & 7) + ((lane >> 3) & 1) * 8;
#pragma unroll
                for (int nf2 = 0; nf2 < 2; ++nf2) {
                    int bch = wn * 4 + nf2 * 2 + ((lane >> 4) & 1);
                    uint32_t so = (uint32_t)(brow * 256 + ((bch ^ (brow & 7)) * 16));
                    ldm_x4_t(bh[nf2], sb + OSC + so);
                    ldm_x4_t(bl[nf2], sb + OSC + 8192 + so);
                }
#pragma unroll
                for (int mf = 0; mf < 4; ++mf)
#pragma unroll
                    for (int nf = 0; nf < 4; ++nf)
                        mma3(oAcc[mf][nf], ah[mf], al[mf],
                             bh[nf >> 1][(nf & 1) * 2], bh[nf >> 1][(nf & 1) * 2 + 1],
                             bl[nf >> 1][(nf & 1) * 2], bl[nf >> 1][(nf & 1) * 2 + 1]);
            }
        }
    }

    {
        const int r0 = lane >> 2;
        const int c0 = (lane & 3) * 2;
#pragma unroll
        for (int mf = 0; mf < 4; ++mf) {
            int i0 = wm * 64 + mf * 16 + r0;
            int i1 = i0 + 8;
            float g0 = gp[i0], g1 = gp[i1];
#pragma unroll
            for (int nf = 0; nf < 4; ++nf) {
                int j0 = wn * 32 + nf * 8 + c0;
                int j1 = j0 + 1;
                float d0 = (i0 >= j0) ? pAcc[mf][nf][0] * gp[i0 - j0] : 0.0f;
                float d1 = (i0 >= j1) ? pAcc[mf][nf][1] * gp[i0 - j1] : 0.0f;
                float d2 = (i1 >= j0) ? pAcc[mf][nf][2] * gp[i1 - j0] : 0.0f;
                float d3 = (i1 >= j1) ? pAcc[mf][nf][3] * gp[i1 - j1] : 0.0f;
                uint32_t h0, l0, h1, l1;
                split_pair(d0, d1, h0, l0);
                split_pair(d2, d3, h1, l1);
                uint32_t a0 = (uint32_t)(i0 * 256 + (((j0 >> 3) ^ (i0 & 7)) * 16) + (j0 & 7) * 2);
                uint32_t a1 = (uint32_t)(i1 * 256 + (((j0 >> 3) ^ (i1 & 7)) * 16) + (j0 & 7) * 2);
                *reinterpret_cast<uint32_t*>(sm + OP_HI + a0) = h0;
                *reinterpret_cast<uint32_t*>(sm + OP_LO + a0) = l0;
                *reinterpret_cast<uint32_t*>(sm + OP_HI + a1) = h1;
                *reinterpret_cast<uint32_t*>(sm + OP_LO + a1) = l1;
                oAcc[mf][nf][0] *= g0;
                oAcc[mf][nf][1] *= g0;
                oAcc[mf][nf][2] *= g1;
                oAcc[mf][nf][3] *= g1;
            }
        }
    }

    for (int jt = 0; jt < 4; ++jt) {
        __syncthreads();
        copy32x128(OSB,        vh + (size_t)jt * 32 * HN);
        copy32x128(OSB + 8192, vl + (size_t)jt * 32 * HN);
        __syncthreads();
        if (wm == 0 && jt >= 2) continue;
#pragma unroll
        for (int kk = 0; kk < 2; ++kk) {
            const int ks = jt * 2 + kk;
            uint32_t ah[4][4], al[4][4];
            const int arow = lane & 15;
            const int ach  = ks * 2 + (lane >> 4);
#pragma unroll
            for (int mf = 0; mf < 4; ++mf) {
                int row = wm * 64 + mf * 16 + arow;
                uint32_t so = (uint32_t)(row * 256 + ((ach ^ (row & 7)) * 16));
                ldm_x4(ah[mf], sb + OP_HI + so);
                ldm_x4(al[mf], sb + OP_LO + so);
            }
            uint32_t bh[2][4], bl[2][4];
            const int brow = kk * 16 + (lane & 7) + ((lane >> 3) & 1) * 8;
#pragma unroll
            for (int nf2 = 0; nf2 < 2; ++nf2) {
                int bch = wn * 4 + nf2 * 2 + ((lane >> 4) & 1);
                uint32_t so = (uint32_t)(brow * 256 + ((bch ^ (brow & 7)) * 16));
                ldm_x4_t(bh[nf2], sb + OSB + so);
                ldm_x4_t(bl[nf2], sb + OSB + 8192 + so);
            }
#pragma unroll
            for (int mf = 0; mf < 4; ++mf)
#pragma unroll
                for (int nf = 0; nf < 4; ++nf)
                    mma3(oAcc[mf][nf], ah[mf], al[mf],
                         bh[nf >> 1][(nf & 1) * 2], bh[nf >> 1][(nf & 1) * 2 + 1],
                         bl[nf >> 1][(nf & 1) * 2], bl[nf >> 1][(nf & 1) * 2 + 1]);
        }
    }

    {
        const int r0 = lane >> 2;
        const int c0 = (lane & 3) * 2;
#pragma unroll
        for (int mf = 0; mf < 4; ++mf)
#pragma unroll
            for (int nf = 0; nf < 4; ++nf) {
                size_t row = rowbase + wm * 64 + mf * 16 + r0;
                int col = wn * 32 + nf * 8 + c0;
                float2 v0 = {oAcc[mf][nf][0], oAcc[mf][nf][1]};
                float2 v1 = {oAcc[mf][nf][2], oAcc[mf][nf][3]};
                *reinterpret_cast<float2*>(&out[row * HN + col])       = v0;
                *reinterpret_cast<float2*>(&out[(row + 8) * HN + col]) = v1;
            }
    }
}

// ===========================================================================
extern "C" void kernel_launch(void* const* d_in, const int* in_sizes, int n_in,
                              void* d_out, int out_size)
{
    const float* x  = (const float*)d_in[0];
    const float* Wq = (const float*)d_in[1];
    const float* Wk = (const float*)d_in[2];
    const float* Wv = (const float*)d_in[3];
    float* out = (float*)d_out;

    cudaFuncSetAttribute(proj_mma_kernel, cudaFuncAttributeMaxDynamicSharedMemorySize,
                         2 * BUF_SZ);
    cudaFuncSetAttribute(out_mma, cudaFuncAttributeMaxDynamicSharedMemorySize,
                         OUT_SMEM);

    wprep_kernel<<<dim3(CN, 3), HN>>>(Wq, Wk, Wv);
    proj_mma_kernel<<<dim3(3, MN / 128), 256, 2 * BUF_SZ>>>(x);
    chunkkv_mma<<<dim3(NCN, BN), 256>>>();
    scan_kernel<<<(BN * HN * HN + 255) / 256, 256>>>();
    out_mma<<<dim3(NCN, BN), 256, OUT_SMEM>>>(out);
}

// round 16
// speedup vs baseline: 1.1708x; 1.0027x over previous
#include <cuda_runtime.h>
#include <cuda_bf16.h>
#include <math.h>
#include <stdint.h>

// Problem constants: RetentionHead  B=4, T=4096, C=1024, H=128
#define BN 4
#define TN 4096
#define CN 1024
#define HN 128
#define LN 128
#define NCN (TN / LN)          // 32 chunks per batch
#define MN (BN * TN)           // 16384 rows
#define NPROJ 384
#define GAMMA 0.96875f
#define SCALE 0.03125f         // C^-0.5

typedef unsigned long long ull;

// ---------------- mma.sync / ldmatrix / cp.async helpers -------------------
__device__ __forceinline__ uint32_t smem_u32(const void* p) {
    uint32_t a;
    asm("{ .reg .u64 t; cvta.to.shared.u64 t, %1; cvt.u32.u64 %0, t; }" : "=r"(a) : "l"(p));
    return a;
}
__device__ __forceinline__ void cp16(uint32_t s, const void* g) {
    asm volatile("cp.async.cg.shared.global [%0], [%1], 16;" :: "r"(s), "l"(g));
}
__device__ __forceinline__ void cp_commit() {
    asm volatile("cp.async.commit_group;" ::: "memory");
}
__device__ __forceinline__ void ldm_x4(uint32_t* r, uint32_t addr) {
    asm volatile("ldmatrix.sync.aligned.m8n8.x4.shared.b16 {%0,%1,%2,%3}, [%4];"
                 : "=r"(r[0]), "=r"(r[1]), "=r"(r[2]), "=r"(r[3]) : "r"(addr));
}
__device__ __forceinline__ void ldm_x4_t(uint32_t* r, uint32_t addr) {
    asm volatile("ldmatrix.sync.aligned.m8n8.x4.trans.shared.b16 {%0,%1,%2,%3}, [%4];"
                 : "=r"(r[0]), "=r"(r[1]), "=r"(r[2]), "=r"(r[3]) : "r"(addr));
}
__device__ __forceinline__ void mma_bf16(float* d, const uint32_t* a,
                                         uint32_t b0, uint32_t b1) {
    asm volatile(
        "mma.sync.aligned.m16n8k16.row.col.f32.bf16.bf16.f32 "
        "{%0,%1,%2,%3}, {%4,%5,%6,%7}, {%8,%9}, {%0,%1,%2,%3};"
        : "+f"(d[0]), "+f"(d[1]), "+f"(d[2]), "+f"(d[3])
        : "r"(a[0]), "r"(a[1]), "r"(a[2]), "r"(a[3]), "r"(b0), "r"(b1));
}
// 3-product split-2 mma: hi*hi + lo*hi + hi*lo
__device__ __forceinline__ void mma3(float* d, const uint32_t* ah, const uint32_t* al,
                                     uint32_t bh0, uint32_t bh1,
                                     uint32_t bl0, uint32_t bl1) {
    mma_bf16(d, ah, bh0, bh1);
    mma_bf16(d, al, bh0, bh1);
    mma_bf16(d, ah, bl0, bl1);
}
__device__ __forceinline__ uint32_t pack_bf2(float a, float b) {
    __nv_bfloat162 t = __floats2bfloat162_rn(a, b);
    return *reinterpret_cast<uint32_t*>(&t);
}
__device__ __forceinline__ void split_pair(float a, float b, uint32_t& hi, uint32_t& lo) {
    __nv_bfloat16 ah = __float2bfloat16_rn(a);
    __nv_bfloat16 bh = __float2bfloat16_rn(b);
    __nv_bfloat162 hh; hh.x = ah; hh.y = bh;
    hi = *reinterpret_cast<uint32_t*>(&hh);
    lo = pack_bf2(a - __bfloat162float(ah), b - __bfloat162float(bh));
}
__device__ __forceinline__ float bf2sum(uint32_t hw, uint32_t lw, int half) {
    __nv_bfloat162 h = *reinterpret_cast<__nv_bfloat162*>(&hw);
    __nv_bfloat162 l = *reinterpret_cast<__nv_bfloat162*>(&lw);
    return half ? (__bfloat162float(h.y) + __bfloat162float(l.y))
                : (__bfloat162float(h.x) + __bfloat162float(l.x));
}

// ---------------- scratch (device globals) ---------------------------------
__device__ float g_A[BN * NCN * HN * HN];
__device__ __nv_bfloat16 g_qh[MN * HN], g_ql[MN * HN];
__device__ __nv_bfloat16 g_kh[MN * HN], g_kl[MN * HN];
__device__ __nv_bfloat16 g_vh[MN * HN], g_vl[MN * HN];
__device__ __nv_bfloat16 g_Sh[BN * NCN * HN * HN], g_Sl[BN * NCN * HN * HN];
__device__ __nv_bfloat16 g_wt_hi[NPROJ * CN];
__device__ __nv_bfloat16 g_wt_lo[NPROJ * CN];

// ===========================================================================
// Kernel 0: W prep (exact R9)
// ===========================================================================
__global__ void wprep_kernel(const float* __restrict__ Wq,
                             const float* __restrict__ Wk,
                             const float* __restrict__ Wv)
{
    int k = blockIdx.x;
    int mat = blockIdx.y;
    int n = threadIdx.x;
    const float* W = (mat == 0) ? Wq : (mat == 1) ? Wk : Wv;
    float w = W[(size_t)k * HN + n];
    __nv_bfloat16 hi = __float2bfloat16_rn(w);
    size_t off = ((size_t)mat * HN + n) * CN + k;
    g_wt_hi[off] = hi;
    g_wt_lo[off] = __float2bfloat16_rn(w - __bfloat162float(hi));
}

// ===========================================================================
// Kernel 1: projection GEMM (exact R9)
// ===========================================================================
#define OFF_A_HI 0
#define OFF_A_LO 8192
#define OFF_B_HI 16384
#define OFF_B_LO 24576
#define BUF_SZ 32768
#define NKSTEP (CN / 32)

__global__ __launch_bounds__(256) void proj_mma_kernel(const float* __restrict__ x)
{
    extern __shared__ char sm[];
    const uint32_t sbase = smem_u32(sm);
    const int tid  = threadIdx.x;
    const int wid  = tid >> 5;
    const int lane = tid & 31;
    const int wm   = wid & 1;
    const int wn   = wid >> 1;
    const int mat  = blockIdx.x;
    const int m0   = blockIdx.y * 128;
    const int n0   = mat * 128;

    const int arow0 = tid >> 2;
    const int ach0  = tid & 3;

    float acc[4][4][4];
#pragma unroll
    for (int a = 0; a < 4; ++a)
#pragma unroll
        for (int b = 0; b < 4; ++b)
#pragma unroll
            for (int c = 0; c < 4; ++c) acc[a][b][c] = 0.0f;

    float4 apre[2][2];
#pragma unroll
    for (int r = 0; r < 2; ++r) {
        int row = arow0 + 64 * r;
        const float* src = &x[(size_t)(m0 + row) * CN + ach0 * 8];
        apre[r][0] = *reinterpret_cast<const float4*>(src);
        apre[r][1] = *reinterpret_cast<const float4*>(src + 4);
    }
#pragma unroll
    for (int r = 0; r < 2; ++r) {
        int row = arow0 + 64 * r;
        uint32_t so = (uint32_t)(row * 64 + ((ach0 ^ ((row >> 1) & 3)) * 16));
        cp16(sbase + OFF_B_HI + so, &g_wt_hi[(size_t)(n0 + row) * CN + ach0 * 8]);
        cp16(sbase + OFF_B_LO + so, &g_wt_lo[(size_t)(n0 + row) * CN + ach0 * 8]);
    }
    cp_commit();

    for (int ks = 0; ks < NKSTEP; ++ks) {
        const uint32_t sbuf = sbase + (uint32_t)(ks & 1) * BUF_SZ;
        {
#pragma unroll
            for (int r = 0; r < 2; ++r) {
                int row = arow0 + 64 * r;
                float f[8] = {apre[r][0].x, apre[r][0].y, apre[r][0].z, apre[r][0].w,
                              apre[r][1].x, apre[r][1].y, apre[r][1].z, apre[r][1].w};
                uint4 vh, vl;
                uint32_t* ph = &vh.x;
                uint32_t* pl = &vl.x;
#pragma unroll
                for (int q = 0; q < 4; ++q) split_pair(f[2*q], f[2*q+1], ph[q], pl[q]);
                uint32_t so = (uint32_t)(row * 64 + ((ach0 ^ ((row >> 1) & 3)) * 16));
                *reinterpret_cast<uint4*>(sm + (ks & 1) * BUF_SZ + OFF_A_HI + so) = vh;
                *reinterpret_cast<uint4*>(sm + (ks & 1) * BUF_SZ + OFF_A_LO + so) = vl;
            }
        }
        if (ks + 1 < NKSTEP) {
            const int k0n = (ks + 1) * 32;
            const uint32_t snext = sbase + (uint32_t)((ks + 1) & 1) * BUF_SZ;
#pragma unroll
            for (int r = 0; r < 2; ++r) {
                int row = arow0 + 64 * r;
                const float* src = &x[(size_t)(m0 + row) * CN + k0n + ach0 * 8];
                apre[r][0] = *reinterpret_cast<const float4*>(src);
                apre[r][1] = *reinterpret_cast<const float4*>(src + 4);
            }
#pragma unroll
            for (int r = 0; r < 2; ++r) {
                int row = arow0 + 64 * r;
                uint32_t so = (uint32_t)(row * 64 + ((ach0 ^ ((row >> 1) & 3)) * 16));
                cp16(snext + OFF_B_HI + so, &g_wt_hi[(size_t)(n0 + row) * CN + k0n + ach0 * 8]);
                cp16(snext + OFF_B_LO + so, &g_wt_lo[(size_t)(n0 + row) * CN + k0n + ach0 * 8]);
            }
            cp_commit();
            asm volatile("cp.async.wait_group 1;" ::: "memory");
        } else {
            asm volatile("cp.async.wait_group 0;" ::: "memory");
        }
        __syncthreads();

#pragma unroll
        for (int kk = 0; kk < 2; ++kk) {
            uint32_t ah[4][4], al[4][4];
            const int arow = lane & 15;
            const int ach  = kk * 2 + (lane >> 4);
#pragma unroll
            for (int mf = 0; mf < 4; ++mf) {
                int row = wm * 64 + mf * 16 + arow;
                uint32_t so = (uint32_t)(row * 64 + ((ach ^ ((row >> 1) & 3)) * 16));
                ldm_x4(ah[mf], sbuf + OFF_A_HI + so);
                ldm_x4(al[mf], sbuf + OFF_A_LO + so);
            }
            uint32_t bh[2][4], bl[2][4];
            const int brow = (lane & 7) + ((lane >> 4) & 1) * 8;
            const int bch  = kk * 2 + ((lane >> 3) & 1);
#pragma unroll
            for (int nf2 = 0; nf2 < 2; ++nf2) {
                int row = wn * 32 + nf2 * 16 + brow;
                uint32_t so = (uint32_t)(row * 64 + ((bch ^ ((row >> 1) & 3)) * 16));
                ldm_x4(bh[nf2], sbuf + OFF_B_HI + so);
                ldm_x4(bl[nf2], sbuf + OFF_B_LO + so);
            }
#pragma unroll
            for (int mf = 0; mf < 4; ++mf)
#pragma unroll
                for (int nf = 0; nf < 4; ++nf)
                    mma3(acc[mf][nf], ah[mf], al[mf],
                         bh[nf >> 1][(nf & 1) * 2], bh[nf >> 1][(nf & 1) * 2 + 1],
                         bl[nf >> 1][(nf & 1) * 2], bl[nf >> 1][(nf & 1) * 2 + 1]);
        }
        __syncthreads();
    }

    const float sc = (mat == 0) ? SCALE : 1.0f;
    __nv_bfloat16* dsth = (mat == 0) ? g_qh : (mat == 1) ? g_kh : g_vh;
    __nv_bfloat16* dstl = (mat == 0) ? g_ql : (mat == 1) ? g_kl : g_vl;
    const int r0 = lane >> 2;
    const int c0 = (lane & 3) * 2;
#pragma unroll
    for (int mf = 0; mf < 4; ++mf) {
#pragma unroll
        for (int nf = 0; nf < 4; ++nf) {
            int row = m0 + wm * 64 + mf * 16 + r0;
            int col = wn * 32 + nf * 8 + c0;
            float d0 = acc[mf][nf][0] * sc, d1 = acc[mf][nf][1] * sc;
            float d2 = acc[mf][nf][2] * sc, d3 = acc[mf][nf][3] * sc;
            uint32_t h0, l0, h1, l1;
            split_pair(d0, d1, h0, l0);
            split_pair(d2, d3, h1, l1);
            *reinterpret_cast<uint32_t*>(&dsth[(size_t)row * HN + col])       = h0;
            *reinterpret_cast<uint32_t*>(&dstl[(size_t)row * HN + col])       = l0;
            *reinterpret_cast<uint32_t*>(&dsth[(size_t)(row + 8) * HN + col]) = h1;
            *reinterpret_cast<uint32_t*>(&dstl[(size_t)(row + 8) * HN + col]) = l1;
        }
    }
}

// ===========================================================================
// Kernel 2: chunkkv via mma, pipelined: register-prefetched K stripes,
// cp.async double-buffered V stripes.  2 syncs/iter (proven-safe skeleton).
// ===========================================================================
#define CKB(b)  ((b) * 32768)
#define CK_KHI 0
#define CK_KLO 8192
#define CK_VHI 16384
#define CK_VLO 24576
#define CK_SMEM 65536

__global__ __launch_bounds__(256) void chunkkv_mma()
{
    extern __shared__ char csm[];
    __shared__ float gp[132];
    const uint32_t sb = smem_u32(csm);

    const int c = blockIdx.x;
    const int b = blockIdx.y;
    const size_t rowbase = (size_t)(b * TN + c * LN);
    const __nv_bfloat16* __restrict__ khp = g_kh + rowbase * HN;
    const __nv_bfloat16* __restrict__ klp = g_kl + rowbase * HN;
    const __nv_bfloat16* __restrict__ vhp = g_vh + rowbase * HN;
    const __nv_bfloat16* __restrict__ vlp = g_vl + rowbase * HN;
    float* __restrict__ ap = g_A + (size_t)(b * NCN + c) * HN * HN;

    const int tid  = threadIdx.x;
    const int wid  = tid >> 5;
    const int lane = tid & 31;
    const int wm   = wid & 1;
    const int wn   = wid >> 1;

    if (tid < 132) gp[tid] = powf(GAMMA, (float)tid);

    // per-thread stripe units: id = tid + 256*r -> row = id>>4 (0..31), ch = id&15
    const int srow0 = tid >> 4;          // r=0 row; r=1 row = srow0+16
    const int sch   = tid & 15;

    // prologue: LDG k(0) -> regs; cp.async v(0) -> buf0
    uint4 kpre_h[2], kpre_l[2];
#pragma unroll
    for (int r = 0; r < 2; ++r) {
        int j = srow0 + 16 * r;
        kpre_h[r] = *reinterpret_cast<const uint4*>(&khp[(size_t)j * HN + sch * 8]);
        kpre_l[r] = *reinterpret_cast<const uint4*>(&klp[(size_t)j * HN + sch * 8]);
    }
#pragma unroll
    for (int r = 0; r < 2; ++r) {
        int row = srow0 + 16 * r;
        uint32_t dst = (uint32_t)(row * 256 + ((sch ^ (row & 7)) * 16));
        cp16(sb + CKB(0) + CK_VHI + dst, &vhp[(size_t)row * HN + sch * 8]);
        cp16(sb + CKB(0) + CK_VLO + dst, &vlp[(size_t)row * HN + sch * 8]);
    }
    cp_commit();
    __syncthreads();     // gp visible

    float acc[4][4][4];
#pragma unroll
    for (int a = 0; a < 4; ++a)
#pragma unroll
        for (int e = 0; e < 4; ++e)
#pragma unroll
            for (int f = 0; f < 4; ++f) acc[a][e][f] = 0.0f;

    for (int jt = 0; jt < 4; ++jt) {
        const uint32_t kb = sb + CKB(jt & 1);
        // decay + split + STS k(jt) from prefetched regs
#pragma unroll
        for (int r = 0; r < 2; ++r) {
            int row = srow0 + 16 * r;
            int j   = jt * 32 + row;
            float w = gp[LN - j];
            const uint32_t* hw = &kpre_h[r].x;
            const uint32_t* lw = &kpre_l[r].x;
            uint4 vh4, vl4;
            uint32_t* ph = &vh4.x;
            uint32_t* pl = &vl4.x;
#pragma unroll
            for (int q = 0; q < 4; ++q) {
                float f0 = bf2sum(hw[q], lw[q], 0) * w;
                float f1 = bf2sum(hw[q], lw[q], 1) * w;
                split_pair(f0, f1, ph[q], pl[q]);
            }
            uint32_t dst = (uint32_t)(row * 256 + ((sch ^ (row & 7)) * 16));
            *reinterpret_cast<uint4*>(csm + CKB(jt & 1) + CK_KHI + dst) = vh4;
            *reinterpret_cast<uint4*>(csm + CKB(jt & 1) + CK_KLO + dst) = vl4;
        }
        // prefetch next stripes
        if (jt + 1 < 4) {
            const int jn = jt + 1;
#pragma unroll
            for (int r = 0; r < 2; ++r) {
                int j = jn * 32 + srow0 + 16 * r;
                kpre_h[r] = *reinterpret_cast<const uint4*>(&khp[(size_t)j * HN + sch * 8]);
                kpre_l[r] = *reinterpret_cast<const uint4*>(&klp[(size_t)j * HN + sch * 8]);
            }
#pragma unroll
            for (int r = 0; r < 2; ++r) {
                int row = srow0 + 16 * r;
                int j   = jn * 32 + row;
                uint32_t dst = (uint32_t)(row * 256 + ((sch ^ (row & 7)) * 16));
                cp16(sb + CKB(jn & 1) + CK_VHI + dst, &vhp[(size_t)j * HN + sch * 8]);
                cp16(sb + CKB(jn & 1) + CK_VLO + dst, &vlp[(size_t)j * HN + sch * 8]);
            }
            cp_commit();
            asm volatile("cp.async.wait_group 1;" ::: "memory");
        } else {
            asm volatile("cp.async.wait_group 0;" ::: "memory");
        }
        __syncthreads();

#pragma unroll
        for (int kk = 0; kk < 2; ++kk) {
            uint32_t ah[4][4], al[4][4];
            const int arow = kk * 16 + (lane & 7) + ((lane >> 4) & 1) * 8;
#pragma unroll
            for (int mf = 0; mf < 4; ++mf) {
                int ach = wm * 8 + mf * 2 + ((lane >> 3) & 1);
                uint32_t so = (uint32_t)(arow * 256 + ((ach ^ (arow & 7)) * 16));
                ldm_x4_t(ah[mf], kb + CK_KHI + so);
                ldm_x4_t(al[mf], kb + CK_KLO + so);
            }
            uint32_t bh[2][4], bl[2][4];
            const int brow = kk * 16 + (lane & 7) + ((lane >> 3) & 1) * 8;
#pragma unroll
            for (int nf2 = 0; nf2 < 2; ++nf2) {
                int bch = wn * 4 + nf2 * 2 + ((lane >> 4) & 1);
                uint32_t so = (uint32_t)(brow * 256 + ((bch ^ (brow & 7)) * 16));
                ldm_x4_t(bh[nf2], kb + CK_VHI + so);
                ldm_x4_t(bl[nf2], kb + CK_VLO + so);
            }
#pragma unroll
            for (int mf = 0; mf < 4; ++mf)
#pragma unroll
                for (int nf = 0; nf < 4; ++nf)
                    mma3(acc[mf][nf], ah[mf], al[mf],
                         bh[nf >> 1][(nf & 1) * 2], bh[nf >> 1][(nf & 1) * 2 + 1],
                         bl[nf >> 1][(nf & 1) * 2], bl[nf >> 1][(nf & 1) * 2 + 1]);
        }
        __syncthreads();   // guard: mma(jt) reads retire before buf[(jt+1)&1] writes next iter
    }

    const int r0 = lane >> 2;
    const int c0 = (lane & 3) * 2;
#pragma unroll
    for (int mf = 0; mf < 4; ++mf)
#pragma unroll
        for (int nf = 0; nf < 4; ++nf) {
            int row = wm * 64 + mf * 16 + r0;
            int col = wn * 32 + nf * 8 + c0;
            float2 v0 = {acc[mf][nf][0], acc[mf][nf][1]};
            float2 v1 = {acc[mf][nf][2], acc[mf][nf][3]};
            *reinterpret_cast<float2*>(&ap[(size_t)row * HN + col])       = v0;
            *reinterpret_cast<float2*>(&ap[(size_t)(row + 8) * HN + col]) = v1;
        }
}

// ===========================================================================
// Kernel 3: prefix scan (exact R9)
// ===========================================================================
__global__ void scan_kernel()
{
    int idx = blockIdx.x * blockDim.x + threadIdx.x;
    if (idx >= BN * HN * HN) return;
    int b = idx / (HN * HN);
    int e = idx % (HN * HN);
    const float gL = powf(GAMMA, (float)LN);
    const size_t base = (size_t)b * NCN * HN * HN + e;

    float a[NCN];
#pragma unroll
    for (int c = 0; c < NCN; ++c)
        a[c] = g_A[base + (size_t)c * HN * HN];

    float S = 0.0f;
#pragma unroll
    for (int c = 0; c < NCN; ++c) {
        size_t off = base + (size_t)c * HN * HN;
        __nv_bfloat16 hi = __float2bfloat16_rn(S);
        g_Sh[off] = hi;
        g_Sl[off] = __float2bfloat16_rn(S - __bfloat162float(hi));
        S = fmaf(S, gL, a[c]);
    }
}

// ===========================================================================
// Kernel 4: out via mma, fused phase 1 + 2b, cp.async double-buffered staging.
// ===========================================================================
#define OP_HI 0
#define OP_LO 32768
#define STG(bb) (65536 + (bb) * 49152)
#define SG_A 0
#define SG_B 16384
#define SG_C 32768
#define OUT_SMEM (65536 + 2 * 49152)

__global__ __launch_bounds__(256) void out_mma(float* __restrict__ out)
{
    extern __shared__ char sm[];
    __shared__ float gp[128];
    const uint32_t sb = smem_u32(sm);

    const int c = blockIdx.x;
    const int b = blockIdx.y;
    const size_t rowbase = (size_t)(b * TN + c * LN);
    const __nv_bfloat16* __restrict__ qh = g_qh + rowbase * HN;
    const __nv_bfloat16* __restrict__ ql = g_ql + rowbase * HN;
    const __nv_bfloat16* __restrict__ kh = g_kh + rowbase * HN;
    const __nv_bfloat16* __restrict__ kl = g_kl + rowbase * HN;
    const __nv_bfloat16* __restrict__ vh = g_vh + rowbase * HN;
    const __nv_bfloat16* __restrict__ vl = g_vl + rowbase * HN;
    const __nv_bfloat16* __restrict__ Sh = g_Sh + (size_t)(b * NCN + c) * HN * HN;
    const __nv_bfloat16* __restrict__ Sl = g_Sl + (size_t)(b * NCN + c) * HN * HN;

    const int tid  = threadIdx.x;
    const int wid  = tid >> 5;
    const int lane = tid & 31;
    const int wm   = wid & 1;
    const int wn   = wid >> 1;

    if (tid < 128) gp[tid] = powf(GAMMA, (float)tid);

    // cp.async staging copies (pure LDG->swizzled-STS)
    auto cpy128x32 = [&](uint32_t dstOff, const __nv_bfloat16* src, int h0) {
#pragma unroll
        for (int r = 0; r < 2; ++r) {
            int id  = tid + 256 * r;
            int row = id >> 2;
            int ch  = id & 3;
            cp16(sb + dstOff + row * 64 + ((ch ^ ((row >> 1) & 3)) * 16),
                 &src[(size_t)row * HN + h0 + ch * 8]);
        }
    };
    auto cpy32x128 = [&](uint32_t dstOff, const __nv_bfloat16* src) {
#pragma unroll
        for (int r = 0; r < 2; ++r) {
            int id  = tid + 256 * r;
            int row = id >> 4;
            int ch  = id & 15;
            cp16(sb + dstOff + row * 256 + ((ch ^ (row & 7)) * 16),
                 &src[(size_t)row * HN + ch * 8]);
        }
    };
    auto stage12 = [&](int ks, int bb) {
        cpy128x32(STG(bb) + SG_A,        qh, ks * 32);
        cpy128x32(STG(bb) + SG_A + 8192, ql, ks * 32);
        cpy128x32(STG(bb) + SG_B,        kh, ks * 32);
        cpy128x32(STG(bb) + SG_B + 8192, kl, ks * 32);
        cpy32x128(STG(bb) + SG_C,        Sh + (size_t)ks * 32 * HN);
        cpy32x128(STG(bb) + SG_C + 8192, Sl + (size_t)ks * 32 * HN);
        cp_commit();
    };
    auto stageV = [&](int jt, int bb) {
        cpy32x128(STG(bb) + SG_B,        vh + (size_t)jt * 32 * HN);
        cpy32x128(STG(bb) + SG_B + 8192, vl + (size_t)jt * 32 * HN);
        cp_commit();
    };

    // ---------------- fused phase 1 + 2b: P = Q K^T, O = Q S ---------------
    float pAcc[4][4][4], oAcc[4][4][4];
#pragma unroll
    for (int a = 0; a < 4; ++a)
#pragma unroll
        for (int e = 0; e < 4; ++e)
#pragma unroll
            for (int f = 0; f < 4; ++f) { pAcc[a][e][f] = 0.0f; oAcc[a][e][f] = 0.0f; }

    const bool p1skip = (wm == 0 && wn >= 2);
    stage12(0, 0);
    for (int ks = 0; ks < 4; ++ks) {
        if (ks + 1 < 4) {
            stage12(ks + 1, (ks + 1) & 1);
            asm volatile("cp.async.wait_group 1;" ::: "memory");
        } else {
            asm volatile("cp.async.wait_group 0;" ::: "memory");
        }
        __syncthreads();
        const uint32_t sg = sb + STG(ks & 1);
#pragma unroll
        for (int kk = 0; kk < 2; ++kk) {
            uint32_t ah[4][4], al[4][4];
            const int arow = lane & 15;
            const int ach  = kk * 2 + (lane >> 4);
#pragma unroll
            for (int mf = 0; mf < 4; ++mf) {
                int row = wm * 64 + mf * 16 + arow;
                uint32_t so = (uint32_t)(row * 64 + ((ach ^ ((row >> 1) & 3)) * 16));
                ldm_x4(ah[mf], sg + SG_A + so);
                ldm_x4(al[mf], sg + SG_A + 8192 + so);
            }
            if (!p1skip) {
                uint32_t bh[2][4], bl[2][4];
                const int brow = (lane & 7) + ((lane >> 4) & 1) * 8;
                const int bch  = kk * 2 + ((lane >> 3) & 1);
#pragma unroll
                for (int nf2 = 0; nf2 < 2; ++nf2) {
                    int row = wn * 32 + nf2 * 16 + brow;
                    uint32_t so = (uint32_t)(row * 64 + ((bch ^ ((row >> 1) & 3)) * 16));
                    ldm_x4(bh[nf2], sg + SG_B + so);
                    ldm_x4(bl[nf2], sg + SG_B + 8192 + so);
                }
#pragma unroll
                for (int mf = 0; mf < 4; ++mf)
#pragma unroll
                    for (int nf = 0; nf < 4; ++nf)
                        mma3(pAcc[mf][nf], ah[mf], al[mf],
                             bh[nf >> 1][(nf & 1) * 2], bh[nf >> 1][(nf & 1) * 2 + 1],
                             bl[nf >> 1][(nf & 1) * 2], bl[nf >> 1][(nf & 1) * 2 + 1]);
            }
            {
                uint32_t bh[2][4], bl[2][4];
                const int brow = kk * 16 + (lane & 7) + ((lane >> 3) & 1) * 8;
#pragma unroll
                for (int nf2 = 0; nf2 < 2; ++nf2) {
                    int bch = wn * 4 + nf2 * 2 + ((lane >> 4) & 1);
                    uint32_t so = (uint32_t)(brow * 256 + ((bch ^ (brow & 7)) * 16));
                    ldm_x4_t(bh[nf2], sg + SG_C + so);
                    ldm_x4_t(bl[nf2], sg + SG_C + 8192 + so);
                }
#pragma unroll
                for (int mf = 0; mf < 4; ++mf)
#pragma unroll
                    for (int nf = 0; nf < 4; ++nf)
                        mma3(oAcc[mf][nf], ah[mf], al[mf],
                             bh[nf >> 1][(nf & 1) * 2], bh[nf >> 1][(nf & 1) * 2 + 1],
                             bl[nf >> 1][(nf & 1) * 2], bl[nf >> 1][(nf & 1) * 2 + 1]);
            }
        }
        __syncthreads();   // guard: mma(ks) reads retire before next-iter prefetch
    }

    // ---------------- mask + split + store P to smem; scale O --------------
    {
        const int r0 = lane >> 2;
        const int c0 = (lane & 3) * 2;
#pragma unroll
        for (int mf = 0; mf < 4; ++mf) {
            int i0 = wm * 64 + mf * 16 + r0;
            int i1 = i0 + 8;
            float g0 = gp[i0], g1 = gp[i1];
#pragma unroll
            for (int nf = 0; nf < 4; ++nf) {
                int j0 = wn * 32 + nf * 8 + c0;
                int j1 = j0 + 1;
                float d0 = (i0 >= j0) ? pAcc[mf][nf][0] * gp[i0 - j0] : 0.0f;
                float d1 = (i0 >= j1) ? pAcc[mf][nf][1] * gp[i0 - j1] : 0.0f;
                float d2 = (i1 >= j0) ? pAcc[mf][nf][2] * gp[i1 - j0] : 0.0f;
                float d3 = (i1 >= j1) ? pAcc[mf][nf][3] * gp[i1 - j1] : 0.0f;
                uint32_t h0, l0, h1, l1;
                split_pair(d0, d1, h0, l0);
                split_pair(d2, d3, h1, l1);
                uint32_t a0 = (uint32_t)(i0 * 256 + (((j0 >> 3) ^ (i0 & 7)) * 16) + (j0 & 7) * 2);
                uint32_t a1 = (uint32_t)(i1 * 256 + (((j0 >> 3) ^ (i1 & 7)) * 16) + (j0 & 7) * 2);
                *reinterpret_cast<uint32_t*>(sm + OP_HI + a0) = h0;
                *reinterpret_cast<uint32_t*>(sm + OP_LO + a0) = l0;
                *reinterpret_cast<uint32_t*>(sm + OP_HI + a1) = h1;
                *reinterpret_cast<uint32_t*>(sm + OP_LO + a1) = l1;
                oAcc[mf][nf][0] *= g0;
                oAcc[mf][nf][1] *= g0;
                oAcc[mf][nf][2] *= g1;
                oAcc[mf][nf][3] *= g1;
            }
        }
    }

    // ---------------- phase 2a: O += P @ V ---------------------------------
    stageV(0, 0);
    for (int jt = 0; jt < 4; ++jt) {
        if (jt + 1 < 4) {
            stageV(jt + 1, (jt + 1) & 1);
            asm volatile("cp.async.wait_group 1;" ::: "memory");
        } else {
            asm volatile("cp.async.wait_group 0;" ::: "memory");
        }
        __syncthreads();   // V(jt) + P stores visible
        if (!(wm == 0 && jt >= 2)) {
            const uint32_t sg = sb + STG(jt & 1);
#pragma unroll
            for (int kk = 0; kk < 2; ++kk) {
                const int ks = jt * 2 + kk;
                uint32_t ah[4][4], al[4][4];
                const int arow = lane & 15;
                const int ach  = ks * 2 + (lane >> 4);
#pragma unroll
                for (int mf = 0; mf < 4; ++mf) {
                    int row = wm * 64 + mf * 16 + arow;
                    uint32_t so = (uint32_t)(row * 256 + ((ach ^ (row & 7)) * 16));
                    ldm_x4(ah[mf], sb + OP_HI + so);
                    ldm_x4(al[mf], sb + OP_LO + so);
                }
                uint32_t bh[2][4], bl[2][4];
                const int brow = kk * 16 + (lane & 7) + ((lane >> 3) & 1) * 8;
#pragma unroll
                for (int nf2 = 0; nf2 < 2; ++nf2) {
                    int bch = wn * 4 + nf2 * 2 + ((lane >> 4) & 1);
                    uint32_t so = (uint32_t)(brow * 256 + ((bch ^ (brow & 7)) * 16));
                    ldm_x4_t(bh[nf2], sg + SG_B + so);
                    ldm_x4_t(bl[nf2], sg + SG_B + 8192 + so);
                }
#pragma unroll
                for (int mf = 0; mf < 4; ++mf)
#pragma unroll
                    for (int nf = 0; nf < 4; ++nf)
                        mma3(oAcc[mf][nf], ah[mf], al[mf],
                             bh[nf >> 1][(nf & 1) * 2], bh[nf >> 1][(nf & 1) * 2 + 1],
                             bl[nf >> 1][(nf & 1) * 2], bl[nf >> 1][(nf & 1) * 2 + 1]);
            }
        }
        __syncthreads();   // guard before next-iter V prefetch into other buf
    }

    // ---------------- store O ----------------------------------------------
    {
        const int r0 = lane >> 2;
        const int c0 = (lane & 3) * 2;
#pragma unroll
        for (int mf = 0; mf < 4; ++mf)
#pragma unroll
            for (int nf = 0; nf < 4; ++nf) {
                size_t row = rowbase + wm * 64 + mf * 16 + r0;
                int col = wn * 32 + nf * 8 + c0;
                float2 v0 = {oAcc[mf][nf][0], oAcc[mf][nf][1]};
                float2 v1 = {oAcc[mf][nf][2], oAcc[mf][nf][3]};
                *reinterpret_cast<float2*>(&out[row * HN + col])       = v0;
                *reinterpret_cast<float2*>(&out[(row + 8) * HN + col]) = v1;
            }
    }
}

// ===========================================================================
extern "C" void kernel_launch(void* const* d_in, const int* in_sizes, int n_in,
                              void* d_out, int out_size)
{
    const float* x  = (const float*)d_in[0];
    const float* Wq = (const float*)d_in[1];
    const float* Wk = (const float*)d_in[2];
    const float* Wv = (const float*)d_in[3];
    float* out = (float*)d_out;

    cudaFuncSetAttribute(proj_mma_kernel, cudaFuncAttributeMaxDynamicSharedMemorySize,
                         2 * BUF_SZ);
    cudaFuncSetAttribute(chunkkv_mma, cudaFuncAttributeMaxDynamicSharedMemorySize,
                         CK_SMEM);
    cudaFuncSetAttribute(out_mma, cudaFuncAttributeMaxDynamicSharedMemorySize,
                         OUT_SMEM);

    wprep_kernel<<<dim3(CN, 3), HN>>>(Wq, Wk, Wv);
    proj_mma_kernel<<<dim3(3, MN / 128), 256, 2 * BUF_SZ>>>(x);
    chunkkv_mma<<<dim3(NCN, BN), 256, CK_SMEM>>>();
    scan_kernel<<<(BN * HN * HN + 255) / 256, 256>>>();
    out_mma<<<dim3(NCN, BN), 256, OUT_SMEM>>>(out);
}

// round 17
// speedup vs baseline: 1.5739x; 1.3444x over previous
#include <cuda_runtime.h>
#include <cuda_fp16.h>
#include <math.h>
#include <stdint.h>

// Problem constants: RetentionHead  B=4, T=4096, C=1024, H=128
#define BN 4
#define TN 4096
#define CN 1024
#define HN 128
#define LN 128
#define NCN (TN / LN)          // 32 chunks per batch
#define MN (BN * TN)           // 16384 rows
#define NPROJ 384
#define GAMMA 0.96875f
#define SCALE 0.03125f         // C^-0.5

typedef unsigned long long ull;

// ---------------- mma.sync / ldmatrix / cp.async helpers -------------------
__device__ __forceinline__ uint32_t smem_u32(const void* p) {
    uint32_t a;
    asm("{ .reg .u64 t; cvta.to.shared.u64 t, %1; cvt.u32.u64 %0, t; }" : "=r"(a) : "l"(p));
    return a;
}
__device__ __forceinline__ void cp16(uint32_t s, const void* g) {
    asm volatile("cp.async.cg.shared.global [%0], [%1], 16;" :: "r"(s), "l"(g));
}
__device__ __forceinline__ void cp_commit() {
    asm volatile("cp.async.commit_group;" ::: "memory");
}
__device__ __forceinline__ void ldm_x4(uint32_t* r, uint32_t addr) {
    asm volatile("ldmatrix.sync.aligned.m8n8.x4.shared.b16 {%0,%1,%2,%3}, [%4];"
                 : "=r"(r[0]), "=r"(r[1]), "=r"(r[2]), "=r"(r[3]) : "r"(addr));
}
__device__ __forceinline__ void ldm_x4_t(uint32_t* r, uint32_t addr) {
    asm volatile("ldmatrix.sync.aligned.m8n8.x4.trans.shared.b16 {%0,%1,%2,%3}, [%4];"
                 : "=r"(r[0]), "=r"(r[1]), "=r"(r[2]), "=r"(r[3]) : "r"(addr));
}
__device__ __forceinline__ void mma_f16(float* d, const uint32_t* a,
                                        uint32_t b0, uint32_t b1) {
    asm volatile(
        "mma.sync.aligned.m16n8k16.row.col.f32.f16.f16.f32 "
        "{%0,%1,%2,%3}, {%4,%5,%6,%7}, {%8,%9}, {%0,%1,%2,%3};"
        : "+f"(d[0]), "+f"(d[1]), "+f"(d[2]), "+f"(d[3])
        : "r"(a[0]), "r"(a[1]), "r"(a[2]), "r"(a[3]), "r"(b0), "r"(b1));
}
// 2-product fp16 split: (A_hi + A_lo) * B
__device__ __forceinline__ void mma2(float* d, const uint32_t* ah, const uint32_t* al,
                                     uint32_t b0, uint32_t b1) {
    mma_f16(d, ah, b0, b1);
    mma_f16(d, al, b0, b1);
}
__device__ __forceinline__ uint32_t pack_h2(float a, float b) {
    __half2 t = __floats2half2_rn(a, b);
    return *reinterpret_cast<uint32_t*>(&t);
}
__device__ __forceinline__ void split_pair(float a, float b, uint32_t& hi, uint32_t& lo) {
    __half ah = __float2half_rn(a);
    __half bh = __float2half_rn(b);
    __half2 hh; hh.x = ah; hh.y = bh;
    hi = *reinterpret_cast<uint32_t*>(&hh);
    lo = pack_h2(a - __half2float(ah), b - __half2float(bh));
}
__device__ __forceinline__ float h2sum(uint32_t hw, uint32_t lw, int hsel) {
    __half2 h = *reinterpret_cast<__half2*>(&hw);
    __half2 l = *reinterpret_cast<__half2*>(&lw);
    return hsel ? (__half2float(h.y) + __half2float(l.y))
                : (__half2float(h.x) + __half2float(l.x));
}

// ---------------- scratch (device globals) ---------------------------------
__device__ float g_A[BN * NCN * HN * HN];
__device__ __half g_qh[MN * HN], g_ql[MN * HN];
__device__ __half g_kh[MN * HN], g_kl[MN * HN];
__device__ __half g_vh[MN * HN], g_vl[MN * HN];   // vl unused (kept for symmetry)
__device__ __half g_Sh[BN * NCN * HN * HN];
__device__ __half g_wt_hi[NPROJ * CN];

// ===========================================================================
// Kernel 0: W prep — transpose fp32 W[k][n] -> single fp16 [mat*128+n][k]
// ===========================================================================
__global__ void wprep_kernel(const float* __restrict__ Wq,
                             const float* __restrict__ Wk,
                             const float* __restrict__ Wv)
{
    int k = blockIdx.x;
    int mat = blockIdx.y;
    int n = threadIdx.x;
    const float* W = (mat == 0) ? Wq : (mat == 1) ? Wk : Wv;
    float w = W[(size_t)k * HN + n];
    g_wt_hi[((size_t)mat * HN + n) * CN + k] = __float2half_rn(w);
}

// ===========================================================================
// Kernel 1: projection GEMM, fp16 split-2 (A split, B single).
// ===========================================================================
#define OFF_A_HI 0
#define OFF_A_LO 8192
#define OFF_B_HI 16384
#define BUF_SZ 32768
#define NKSTEP (CN / 32)

__global__ __launch_bounds__(256) void proj_mma_kernel(const float* __restrict__ x)
{
    extern __shared__ char sm[];
    const uint32_t sbase = smem_u32(sm);
    const int tid  = threadIdx.x;
    const int wid  = tid >> 5;
    const int lane = tid & 31;
    const int wm   = wid & 1;
    const int wn   = wid >> 1;
    const int mat  = blockIdx.x;
    const int m0   = blockIdx.y * 128;
    const int n0   = mat * 128;

    const int arow0 = tid >> 2;
    const int ach0  = tid & 3;

    float acc[4][4][4];
#pragma unroll
    for (int a = 0; a < 4; ++a)
#pragma unroll
        for (int b = 0; b < 4; ++b)
#pragma unroll
            for (int c = 0; c < 4; ++c) acc[a][b][c] = 0.0f;

    float4 apre[2][2];
#pragma unroll
    for (int r = 0; r < 2; ++r) {
        int row = arow0 + 64 * r;
        const float* src = &x[(size_t)(m0 + row) * CN + ach0 * 8];
        apre[r][0] = *reinterpret_cast<const float4*>(src);
        apre[r][1] = *reinterpret_cast<const float4*>(src + 4);
    }
#pragma unroll
    for (int r = 0; r < 2; ++r) {
        int row = arow0 + 64 * r;
        uint32_t so = (uint32_t)(row * 64 + ((ach0 ^ ((row >> 1) & 3)) * 16));
        cp16(sbase + OFF_B_HI + so, &g_wt_hi[(size_t)(n0 + row) * CN + ach0 * 8]);
    }
    cp_commit();

    for (int ks = 0; ks < NKSTEP; ++ks) {
        const uint32_t sbuf = sbase + (uint32_t)(ks & 1) * BUF_SZ;
        {
#pragma unroll
            for (int r = 0; r < 2; ++r) {
                int row = arow0 + 64 * r;
                float f[8] = {apre[r][0].x, apre[r][0].y, apre[r][0].z, apre[r][0].w,
                              apre[r][1].x, apre[r][1].y, apre[r][1].z, apre[r][1].w};
                uint4 vh, vl;
                uint32_t* ph = &vh.x;
                uint32_t* pl = &vl.x;
#pragma unroll
                for (int q = 0; q < 4; ++q) split_pair(f[2*q], f[2*q+1], ph[q], pl[q]);
                uint32_t so = (uint32_t)(row * 64 + ((ach0 ^ ((row >> 1) & 3)) * 16));
                *reinterpret_cast<uint4*>(sm + (ks & 1) * BUF_SZ + OFF_A_HI + so) = vh;
                *reinterpret_cast<uint4*>(sm + (ks & 1) * BUF_SZ + OFF_A_LO + so) = vl;
            }
        }
        if (ks + 1 < NKSTEP) {
            const int k0n = (ks + 1) * 32;
            const uint32_t snext = sbase + (uint32_t)((ks + 1) & 1) * BUF_SZ;
#pragma unroll
            for (int r = 0; r < 2; ++r) {
                int row = arow0 + 64 * r;
                const float* src = &x[(size_t)(m0 + row) * CN + k0n + ach0 * 8];
                apre[r][0] = *reinterpret_cast<const float4*>(src);
                apre[r][1] = *reinterpret_cast<const float4*>(src + 4);
            }
#pragma unroll
            for (int r = 0; r < 2; ++r) {
                int row = arow0 + 64 * r;
                uint32_t so = (uint32_t)(row * 64 + ((ach0 ^ ((row >> 1) & 3)) * 16));
                cp16(snext + OFF_B_HI + so, &g_wt_hi[(size_t)(n0 + row) * CN + k0n + ach0 * 8]);
            }
            cp_commit();
            asm volatile("cp.async.wait_group 1;" ::: "memory");
        } else {
            asm volatile("cp.async.wait_group 0;" ::: "memory");
        }
        __syncthreads();

#pragma unroll
        for (int kk = 0; kk < 2; ++kk) {
            uint32_t ah[4][4], al[4][4];
            const int arow = lane & 15;
            const int ach  = kk * 2 + (lane >> 4);
#pragma unroll
            for (int mf = 0; mf < 4; ++mf) {
                int row = wm * 64 + mf * 16 + arow;
                uint32_t so = (uint32_t)(row * 64 + ((ach ^ ((row >> 1) & 3)) * 16));
                ldm_x4(ah[mf], sbuf + OFF_A_HI + so);
                ldm_x4(al[mf], sbuf + OFF_A_LO + so);
            }
            uint32_t bh[2][4];
            const int brow = (lane & 7) + ((lane >> 4) & 1) * 8;
            const int bch  = kk * 2 + ((lane >> 3) & 1);
#pragma unroll
            for (int nf2 = 0; nf2 < 2; ++nf2) {
                int row = wn * 32 + nf2 * 16 + brow;
                uint32_t so = (uint32_t)(row * 64 + ((bch ^ ((row >> 1) & 3)) * 16));
                ldm_x4(bh[nf2], sbuf + OFF_B_HI + so);
            }
#pragma unroll
            for (int mf = 0; mf < 4; ++mf)
#pragma unroll
                for (int nf = 0; nf < 4; ++nf)
                    mma2(acc[mf][nf], ah[mf], al[mf],
                         bh[nf >> 1][(nf & 1) * 2], bh[nf >> 1][(nf & 1) * 2 + 1]);
        }
        __syncthreads();
    }

    const float sc = (mat == 0) ? SCALE : 1.0f;
    __half* dsth = (mat == 0) ? g_qh : (mat == 1) ? g_kh : g_vh;
    __half* dstl = (mat == 0) ? g_ql : (mat == 1) ? g_kl : g_vl;
    const int r0 = lane >> 2;
    const int c0 = (lane & 3) * 2;
#pragma unroll
    for (int mf = 0; mf < 4; ++mf) {
#pragma unroll
        for (int nf = 0; nf < 4; ++nf) {
            int row = m0 + wm * 64 + mf * 16 + r0;
            int col = wn * 32 + nf * 8 + c0;
            float d0 = acc[mf][nf][0] * sc, d1 = acc[mf][nf][1] * sc;
            float d2 = acc[mf][nf][2] * sc, d3 = acc[mf][nf][3] * sc;
            uint32_t h0, l0, h1, l1;
            split_pair(d0, d1, h0, l0);
            split_pair(d2, d3, h1, l1);
            *reinterpret_cast<uint32_t*>(&dsth[(size_t)row * HN + col])       = h0;
            *reinterpret_cast<uint32_t*>(&dsth[(size_t)(row + 8) * HN + col]) = h1;
            if (mat != 2) {   // v lo never consumed
                *reinterpret_cast<uint32_t*>(&dstl[(size_t)row * HN + col])       = l0;
                *reinterpret_cast<uint32_t*>(&dstl[(size_t)(row + 8) * HN + col]) = l1;
            }
        }
    }
}

// ===========================================================================
// Kernel 2: chunkkv via mma, fp16 split-2.  A = decayed-k split; B = v single.
// ===========================================================================
#define CKB(b)  ((b) * 32768)
#define CK_KHI 0
#define CK_KLO 8192
#define CK_VHI 16384
#define CK_SMEM 65536

__global__ __launch_bounds__(256) void chunkkv_mma()
{
    extern __shared__ char csm[];
    __shared__ float gp[132];
    const uint32_t sb = smem_u32(csm);

    const int c = blockIdx.x;
    const int b = blockIdx.y;
    const size_t rowbase = (size_t)(b * TN + c * LN);
    const __half* __restrict__ khp = g_kh + rowbase * HN;
    const __half* __restrict__ klp = g_kl + rowbase * HN;
    const __half* __restrict__ vhp = g_vh + rowbase * HN;
    float* __restrict__ ap = g_A + (size_t)(b * NCN + c) * HN * HN;

    const int tid  = threadIdx.x;
    const int wid  = tid >> 5;
    const int lane = tid & 31;
    const int wm   = wid & 1;
    const int wn   = wid >> 1;

    if (tid < 132) gp[tid] = powf(GAMMA, (float)tid);

    const int srow0 = tid >> 4;
    const int sch   = tid & 15;

    uint4 kpre_h[2], kpre_l[2];
#pragma unroll
    for (int r = 0; r < 2; ++r) {
        int j = srow0 + 16 * r;
        kpre_h[r] = *reinterpret_cast<const uint4*>(&khp[(size_t)j * HN + sch * 8]);
        kpre_l[r] = *reinterpret_cast<const uint4*>(&klp[(size_t)j * HN + sch * 8]);
    }
#pragma unroll
    for (int r = 0; r < 2; ++r) {
        int row = srow0 + 16 * r;
        uint32_t dst = (uint32_t)(row * 256 + ((sch ^ (row & 7)) * 16));
        cp16(sb + CKB(0) + CK_VHI + dst, &vhp[(size_t)row * HN + sch * 8]);
    }
    cp_commit();
    __syncthreads();

    float acc[4][4][4];
#pragma unroll
    for (int a = 0; a < 4; ++a)
#pragma unroll
        for (int e = 0; e < 4; ++e)
#pragma unroll
            for (int f = 0; f < 4; ++f) acc[a][e][f] = 0.0f;

    for (int jt = 0; jt < 4; ++jt) {
        const uint32_t kb = sb + CKB(jt & 1);
#pragma unroll
        for (int r = 0; r < 2; ++r) {
            int row = srow0 + 16 * r;
            int j   = jt * 32 + row;
            float w = gp[LN - j];
            const uint32_t* hw = &kpre_h[r].x;
            const uint32_t* lw = &kpre_l[r].x;
            uint4 vh4, vl4;
            uint32_t* ph = &vh4.x;
            uint32_t* pl = &vl4.x;
#pragma unroll
            for (int q = 0; q < 4; ++q) {
                float f0 = h2sum(hw[q], lw[q], 0) * w;
                float f1 = h2sum(hw[q], lw[q], 1) * w;
                split_pair(f0, f1, ph[q], pl[q]);
            }
            uint32_t dst = (uint32_t)(row * 256 + ((sch ^ (row & 7)) * 16));
            *reinterpret_cast<uint4*>(csm + CKB(jt & 1) + CK_KHI + dst) = vh4;
            *reinterpret_cast<uint4*>(csm + CKB(jt & 1) + CK_KLO + dst) = vl4;
        }
        if (jt + 1 < 4) {
            const int jn = jt + 1;
#pragma unroll
            for (int r = 0; r < 2; ++r) {
                int j = jn * 32 + srow0 + 16 * r;
                kpre_h[r] = *reinterpret_cast<const uint4*>(&khp[(size_t)j * HN + sch * 8]);
                kpre_l[r] = *reinterpret_cast<const uint4*>(&klp[(size_t)j * HN + sch * 8]);
            }
#pragma unroll
            for (int r = 0; r < 2; ++r) {
                int row = srow0 + 16 * r;
                int j   = jn * 32 + row;
                uint32_t dst = (uint32_t)(row * 256 + ((sch ^ (row & 7)) * 16));
                cp16(sb + CKB(jn & 1) + CK_VHI + dst, &vhp[(size_t)j * HN + sch * 8]);
            }
            cp_commit();
            asm volatile("cp.async.wait_group 1;" ::: "memory");
        } else {
            asm volatile("cp.async.wait_group 0;" ::: "memory");
        }
        __syncthreads();

#pragma unroll
        for (int kk = 0; kk < 2; ++kk) {
            uint32_t ah[4][4], al[4][4];
            const int arow = kk * 16 + (lane & 7) + ((lane >> 4) & 1) * 8;
#pragma unroll
            for (int mf = 0; mf < 4; ++mf) {
                int ach = wm * 8 + mf * 2 + ((lane >> 3) & 1);
                uint32_t so = (uint32_t)(arow * 256 + ((ach ^ (arow & 7)) * 16));
                ldm_x4_t(ah[mf], kb + CK_KHI + so);
                ldm_x4_t(al[mf], kb + CK_KLO + so);
            }
            uint32_t bh[2][4];
            const int brow = kk * 16 + (lane & 7) + ((lane >> 3) & 1) * 8;
#pragma unroll
            for (int nf2 = 0; nf2 < 2; ++nf2) {
                int bch = wn * 4 + nf2 * 2 + ((lane >> 4) & 1);
                uint32_t so = (uint32_t)(brow * 256 + ((bch ^ (brow & 7)) * 16));
                ldm_x4_t(bh[nf2], kb + CK_VHI + so);
            }
#pragma unroll
            for (int mf = 0; mf < 4; ++mf)
#pragma unroll
                for (int nf = 0; nf < 4; ++nf)
                    mma2(acc[mf][nf], ah[mf], al[mf],
                         bh[nf >> 1][(nf & 1) * 2], bh[nf >> 1][(nf & 1) * 2 + 1]);
        }
        __syncthreads();
    }

    const int r0 = lane >> 2;
    const int c0 = (lane & 3) * 2;
#pragma unroll
    for (int mf = 0; mf < 4; ++mf)
#pragma unroll
        for (int nf = 0; nf < 4; ++nf) {
            int row = wm * 64 + mf * 16 + r0;
            int col = wn * 32 + nf * 8 + c0;
            float2 v0 = {acc[mf][nf][0], acc[mf][nf][1]};
            float2 v1 = {acc[mf][nf][2], acc[mf][nf][3]};
            *reinterpret_cast<float2*>(&ap[(size_t)row * HN + col])       = v0;
            *reinterpret_cast<float2*>(&ap[(size_t)(row + 8) * HN + col]) = v1;
        }
}

// ===========================================================================
// Kernel 3: prefix scan; emits single fp16 S.
// ===========================================================================
__global__ void scan_kernel()
{
    int idx = blockIdx.x * blockDim.x + threadIdx.x;
    if (idx >= BN * HN * HN) return;
    int b = idx / (HN * HN);
    int e = idx % (HN * HN);
    const float gL = powf(GAMMA, (float)LN);
    const size_t base = (size_t)b * NCN * HN * HN + e;

    float a[NCN];
#pragma unroll
    for (int c = 0; c < NCN; ++c)
        a[c] = g_A[base + (size_t)c * HN * HN];

    float S = 0.0f;
#pragma unroll
    for (int c = 0; c < NCN; ++c) {
        g_Sh[base + (size_t)c * HN * HN] = __float2half_rn(S);
        S = fmaf(S, gL, a[c]);
    }
}

// ===========================================================================
// Kernel 4: out via mma, fp16 split-2, fused phase 1 + 2b, cp.async staging.
// ===========================================================================
#define OP_HI 0
#define OP_LO 32768
#define STG(bb) (65536 + (bb) * 32768)
#define SG_A 0
#define SG_B 16384
#define SG_C 24576
#define OUT_SMEM (65536 + 2 * 32768)

__global__ __launch_bounds__(256) void out_mma(float* __restrict__ out)
{
    extern __shared__ char sm[];
    __shared__ float gp[128];
    const uint32_t sb = smem_u32(sm);

    const int c = blockIdx.x;
    const int b = blockIdx.y;
    const size_t rowbase = (size_t)(b * TN + c * LN);
    const __half* __restrict__ qh = g_qh + rowbase * HN;
    const __half* __restrict__ ql = g_ql + rowbase * HN;
    const __half* __restrict__ kh = g_kh + rowbase * HN;
    const __half* __restrict__ vh = g_vh + rowbase * HN;
    const __half* __restrict__ Sh = g_Sh + (size_t)(b * NCN + c) * HN * HN;

    const int tid  = threadIdx.x;
    const int wid  = tid >> 5;
    const int lane = tid & 31;
    const int wm   = wid & 1;
    const int wn   = wid >> 1;

    if (tid < 128) gp[tid] = powf(GAMMA, (float)tid);

    auto cpy128x32 = [&](uint32_t dstOff, const __half* src, int h0) {
#pragma unroll
        for (int r = 0; r < 2; ++r) {
            int id  = tid + 256 * r;
            int row = id >> 2;
            int ch  = id & 3;
            cp16(sb + dstOff + row * 64 + ((ch ^ ((row >> 1) & 3)) * 16),
                 &src[(size_t)row * HN + h0 + ch * 8]);
        }
    };
    auto cpy32x128 = [&](uint32_t dstOff, const __half* src) {
#pragma unroll
        for (int r = 0; r < 2; ++r) {
            int id  = tid + 256 * r;
            int row = id >> 4;
            int ch  = id & 15;
            cp16(sb + dstOff + row * 256 + ((ch ^ (row & 7)) * 16),
                 &src[(size_t)row * HN + ch * 8]);
        }
    };
    auto stage12 = [&](int ks, int bb) {
        cpy128x32(STG(bb) + SG_A,        qh, ks * 32);
        cpy128x32(STG(bb) + SG_A + 8192, ql, ks * 32);
        cpy128x32(STG(bb) + SG_B,        kh, ks * 32);
        cpy32x128(STG(bb) + SG_C,        Sh + (size_t)ks * 32 * HN);
        cp_commit();
    };
    auto stageV = [&](int jt, int bb) {
        cpy32x128(STG(bb) + SG_B, vh + (size_t)jt * 32 * HN);
        cp_commit();
    };

    float pAcc[4][4][4], oAcc[4][4][4];
#pragma unroll
    for (int a = 0; a < 4; ++a)
#pragma unroll
        for (int e = 0; e < 4; ++e)
#pragma unroll
            for (int f = 0; f < 4; ++f) { pAcc[a][e][f] = 0.0f; oAcc[a][e][f] = 0.0f; }

    const bool p1skip = (wm == 0 && wn >= 2);
    stage12(0, 0);
    for (int ks = 0; ks < 4; ++ks) {
        if (ks + 1 < 4) {
            stage12(ks + 1, (ks + 1) & 1);
            asm volatile("cp.async.wait_group 1;" ::: "memory");
        } else {
            asm volatile("cp.async.wait_group 0;" ::: "memory");
        }
        __syncthreads();
        const uint32_t sg = sb + STG(ks & 1);
#pragma unroll
        for (int kk = 0; kk < 2; ++kk) {
            uint32_t ah[4][4], al[4][4];
            const int arow = lane & 15;
            const int ach  = kk * 2 + (lane >> 4);
#pragma unroll
            for (int mf = 0; mf < 4; ++mf) {
                int row = wm * 64 + mf * 16 + arow;
                uint32_t so = (uint32_t)(row * 64 + ((ach ^ ((row >> 1) & 3)) * 16));
                ldm_x4(ah[mf], sg + SG_A + so);
                ldm_x4(al[mf], sg + SG_A + 8192 + so);
            }
            if (!p1skip) {
                uint32_t bh[2][4];
                const int brow = (lane & 7) + ((lane >> 4) & 1) * 8;
                const int bch  = kk * 2 + ((lane >> 3) & 1);
#pragma unroll
                for (int nf2 = 0; nf2 < 2; ++nf2) {
                    int row = wn * 32 + nf2 * 16 + brow;
                    uint32_t so = (uint32_t)(row * 64 + ((bch ^ ((row >> 1) & 3)) * 16));
                    ldm_x4(bh[nf2], sg + SG_B + so);
                }
#pragma unroll
                for (int mf = 0; mf < 4; ++mf)
#pragma unroll
                    for (int nf = 0; nf < 4; ++nf)
                        mma2(pAcc[mf][nf], ah[mf], al[mf],
                             bh[nf >> 1][(nf & 1) * 2], bh[nf >> 1][(nf & 1) * 2 + 1]);
            }
            {
                uint32_t bh[2][4];
                const int brow = kk * 16 + (lane & 7) + ((lane >> 3) & 1) * 8;
#pragma unroll
                for (int nf2 = 0; nf2 < 2; ++nf2) {
                    int bch = wn * 4 + nf2 * 2 + ((lane >> 4) & 1);
                    uint32_t so = (uint32_t)(brow * 256 + ((bch ^ (brow & 7)) * 16));
                    ldm_x4_t(bh[nf2], sg + SG_C + so);
                }
#pragma unroll
                for (int mf = 0; mf < 4; ++mf)
#pragma unroll
                    for (int nf = 0; nf < 4; ++nf)
                        mma2(oAcc[mf][nf], ah[mf], al[mf],
                             bh[nf >> 1][(nf & 1) * 2], bh[nf >> 1][(nf & 1) * 2 + 1]);
            }
        }
        __syncthreads();
    }

    // mask + split + store P to smem; scale O
    {
        const int r0 = lane >> 2;
        const int c0 = (lane & 3) * 2;
#pragma unroll
        for (int mf = 0; mf < 4; ++mf) {
            int i0 = wm * 64 + mf * 16 + r0;
            int i1 = i0 + 8;
            float g0 = gp[i0], g1 = gp[i1];
#pragma unroll
            for (int nf = 0; nf < 4; ++nf) {
                int j0 = wn * 32 + nf * 8 + c0;
                int j1 = j0 + 1;
                float d0 = (i0 >= j0) ? pAcc[mf][nf][0] * gp[i0 - j0] : 0.0f;
                float d1 = (i0 >= j1) ? pAcc[mf][nf][1] * gp[i0 - j1] : 0.0f;
                float d2 = (i1 >= j0) ? pAcc[mf][nf][2] * gp[i1 - j0] : 0.0f;
                float d3 = (i1 >= j1) ? pAcc[mf][nf][3] * gp[i1 - j1] : 0.0f;
                uint32_t h0, l0, h1, l1;
                split_pair(d0, d1, h0, l0);
                split_pair(d2, d3, h1, l1);
                uint32_t a0 = (uint32_t)(i0 * 256 + (((j0 >> 3) ^ (i0 & 7)) * 16) + (j0 & 7) * 2);
                uint32_t a1 = (uint32_t)(i1 * 256 + (((j0 >> 3) ^ (i1 & 7)) * 16) + (j0 & 7) * 2);
                *reinterpret_cast<uint32_t*>(sm + OP_HI + a0) = h0;
                *reinterpret_cast<uint32_t*>(sm + OP_LO + a0) = l0;
                *reinterpret_cast<uint32_t*>(sm + OP_HI + a1) = h1;
                *reinterpret_cast<uint32_t*>(sm + OP_LO + a1) = l1;
                oAcc[mf][nf][0] *= g0;
                oAcc[mf][nf][1] *= g0;
                oAcc[mf][nf][2] *= g1;
                oAcc[mf][nf][3] *= g1;
            }
        }
    }

    // phase 2a: O += P @ V
    stageV(0, 0);
    for (int jt = 0; jt < 4; ++jt) {
        if (jt + 1 < 4) {
            stageV(jt + 1, (jt + 1) & 1);
            asm volatile("cp.async.wait_group 1;" ::: "memory");
        } else {
            asm volatile("cp.async.wait_group 0;" ::: "memory");
        }
        __syncthreads();
        if (!(wm == 0 && jt >= 2)) {
            const uint32_t sg = sb + STG(jt & 1);
#pragma unroll
            for (int kk = 0; kk < 2; ++kk) {
                const int ks = jt * 2 + kk;
                uint32_t ah[4][4], al[4][4];
                const int arow = lane & 15;
                const int ach  = ks * 2 + (lane >> 4);
#pragma unroll
                for (int mf = 0; mf < 4; ++mf) {
                    int row = wm * 64 + mf * 16 + arow;
                    uint32_t so = (uint32_t)(row * 256 + ((ach ^ (row & 7)) * 16));
                    ldm_x4(ah[mf], sb + OP_HI + so);
                    ldm_x4(al[mf], sb + OP_LO + so);
                }
                uint32_t bh[2][4];
                const int brow = kk * 16 + (lane & 7) + ((lane >> 3) & 1) * 8;
#pragma unroll
                for (int nf2 = 0; nf2 < 2; ++nf2) {
                    int bch = wn * 4 + nf2 * 2 + ((lane >> 4) & 1);
                    uint32_t so = (uint32_t)(brow * 256 + ((bch ^ (brow & 7)) * 16));
                    ldm_x4_t(bh[nf2], sg + SG_B + so);
                }
#pragma unroll
                for (int mf = 0; mf < 4; ++mf)
#pragma unroll
                    for (int nf = 0; nf < 4; ++nf)
                        mma2(oAcc[mf][nf], ah[mf], al[mf],
                             bh[nf >> 1][(nf & 1) * 2], bh[nf >> 1][(nf & 1) * 2 + 1]);
            }
        }
        __syncthreads();
    }

    // store O
    {
        const int r0 = lane >> 2;
        const int c0 = (lane & 3) * 2;
#pragma unroll
        for (int mf = 0; mf < 4; ++mf)
#pragma unroll
            for (int nf = 0; nf < 4; ++nf) {
                size_t row = rowbase + wm * 64 + mf * 16 + r0;
                int col = wn * 32 + nf * 8 + c0;
                float2 v0 = {oAcc[mf][nf][0], oAcc[mf][nf][1]};
                float2 v1 = {oAcc[mf][nf][2], oAcc[mf][nf][3]};
                *reinterpret_cast<float2*>(&out[row * HN + col])       = v0;
                *reinterpret_cast<float2*>(&out[(row + 8) * HN + col]) = v1;
            }
    }
}

// ===========================================================================
extern "C" void kernel_launch(void* const* d_in, const int* in_sizes, int n_in,
                              void* d_out, int out_size)
{
    const float* x  = (const float*)d_in[0];
    const float* Wq = (const float*)d_in[1];
    const float* Wk = (const float*)d_in[2];
    const float* Wv = (const float*)d_in[3];
    float* out = (float*)d_out;

    cudaFuncSetAttribute(proj_mma_kernel, cudaFuncAttributeMaxDynamicSharedMemorySize,
                         2 * BUF_SZ);
    cudaFuncSetAttribute(chunkkv_mma, cudaFuncAttributeMaxDynamicSharedMemorySize,
                         CK_SMEM);
    cudaFuncSetAttribute(out_mma, cudaFuncAttributeMaxDynamicSharedMemorySize,
                         OUT_SMEM);

    wprep_kernel<<<dim3(CN, 3), HN>>>(Wq, Wk, Wv);
    proj_mma_kernel<<<dim3(3, MN / 128), 256, 2 * BUF_SZ>>>(x);
    chunkkv_mma<<<dim3(NCN, BN), 256, CK_SMEM>>>();
    scan_kernel<<<(BN * HN * HN + 255) / 256, 256>>>();
    out_mma<<<dim3(NCN, BN), 256, OUT_SMEM>>>(out);
}